// round 9
// baseline (speedup 1.0000x reference)
#include <cuda_runtime.h>
#include <cuda_fp16.h>
#include <cstdint>

#define N_NODES 50000
#define E_EDGES 800000
#define IN_DIM  128
#define H_DIM   96
#define OUT_DIM 64
#define NUM_LAYERS 4
#define NB_SCAN ((N_NODES + 1023) / 1024)
#define HWORDS  48   // 96 channels as half2 words

// ---------------- static device scratch ----------------
__device__ float    g_hfin[N_NODES * H_DIM];                 // final-layer fp32 h
__device__ uint32_t g_hhalf[(size_t)N_NODES * HWORDS];       // h as half2 words
__device__ float    g_agg[(size_t)N_NODES * 2 * H_DIM];
__device__ int      g_counts[N_NODES];
__device__ int      g_offsets[N_NODES + 1];
__device__ int      g_cursor[N_NODES];
__device__ int      g_src_sorted[E_EDGES];
__device__ int      g_pos[E_EDGES];
__device__ float2   g_ews[(size_t)E_EDGES * NUM_LAYERS];
__device__ int      g_bsum[NB_SCAN + 1];
__device__ float    g_zero_bias[H_DIM];

// ---------------- f32x2 packed helpers ----------------
__device__ __forceinline__ double pack2(float lo, float hi) {
    double d;
    asm("mov.b64 %0, {%1, %2};" : "=d"(d) : "f"(lo), "f"(hi));
    return d;
}
__device__ __forceinline__ void fma2(double& acc, double a, double b) {
    asm("fma.rn.f32x2 %0, %1, %2, %0;" : "+d"(acc) : "d"(a), "d"(b));
}
__device__ __forceinline__ float2 unpack2(double d) {
    float lo, hi;
    asm("mov.b64 {%0, %1}, %2;" : "=f"(lo), "=f"(hi) : "d"(d));
    return make_float2(lo, hi);
}

// ---------------- CSR build ----------------
__global__ void hist_kernel(const int* __restrict__ dst) {
    int e = blockIdx.x * blockDim.x + threadIdx.x;
    if (e < E_EDGES) atomicAdd(&g_counts[dst[e]], 1);
}

__global__ void block_scan_kernel() {
    __shared__ int sh[1024];
    int t = threadIdx.x;
    int i = blockIdx.x * 1024 + t;
    int v = (i < N_NODES) ? g_counts[i] : 0;
    sh[t] = v;
    __syncthreads();
    #pragma unroll
    for (int off = 1; off < 1024; off <<= 1) {
        int x = (t >= off) ? sh[t - off] : 0;
        __syncthreads();
        sh[t] += x;
        __syncthreads();
    }
    if (i < N_NODES) g_offsets[i] = sh[t] - v;
    if (t == 1023) g_bsum[blockIdx.x] = sh[1023];
}

__global__ void add_base_kernel() {
    __shared__ int pref[NB_SCAN + 1];
    if (threadIdx.x == 0) {
        int run = 0;
        #pragma unroll
        for (int i = 0; i < NB_SCAN; i++) { pref[i] = run; run += g_bsum[i]; }
        pref[NB_SCAN] = run;
    }
    __syncthreads();
    int i = blockIdx.x * blockDim.x + threadIdx.x;
    if (i < N_NODES) {
        int o = g_offsets[i] + pref[i >> 10];
        g_offsets[i] = o;
        g_cursor[i] = o;
    }
    if (i == N_NODES) g_offsets[N_NODES] = pref[NB_SCAN];
}

// critical-path scatter: permutation + layer-0 weights only
__global__ void scatter_light_kernel(const int* __restrict__ src,
                                     const int* __restrict__ dst,
                                     const float* __restrict__ conv_ew) {
    int e = blockIdx.x * blockDim.x + threadIdx.x;
    if (e >= E_EDGES) return;
    int d = dst[e];
    int pos = atomicAdd(&g_cursor[d], 1);
    g_src_sorted[pos] = src[e];
    g_pos[e] = pos;
    g_ews[(size_t)pos * NUM_LAYERS] = make_float2(conv_ew[e], conv_ew[E_EDGES + e]);
}

// layers 1..3 weights (side stream, overlaps agg0/gemm0)
__global__ void ews_rest_kernel(const float* __restrict__ conv_ew) {
    int e = blockIdx.x * blockDim.x + threadIdx.x;
    if (e >= E_EDGES) return;
    int pos = g_pos[e];
    #pragma unroll
    for (int l = 1; l < NUM_LAYERS; l++) {
        float w0 = conv_ew[(size_t)(l * 2 + 0) * E_EDGES + e];
        float w1 = conv_ew[(size_t)(l * 2 + 1) * E_EDGES + e];
        g_ews[(size_t)pos * NUM_LAYERS + l] = make_float2(w0, w1);
    }
}

// ---------------- register-tiled fp32 GEMM, packed f32x2 FMA (identical to R7) ----------------
template <int TN, bool RELU, bool WF32, bool WHALF>
__global__ void __launch_bounds__(128)
gemm_kernel(const float* __restrict__ A, const float* __restrict__ B,
            const float* __restrict__ bias, float* __restrict__ C,
            uint32_t* __restrict__ Chalf, float* __restrict__ C2,
            int M, int K, int lda, int ldc) {
    constexpr int BN = TN * 16;
    constexpr int BM = 64;
    constexpr int BK = 16;
    constexpr int TM = 8;
    __shared__ float As[BK][BM + 4];
    __shared__ float Bs[BK][BN];

    int tid = threadIdx.x;
    int tx = tid & 15;
    int ty = tid >> 4;
    int blockRow = blockIdx.x * BM;

    double acc[TM / 2][TN];
    #pragma unroll
    for (int i = 0; i < TM / 2; i++)
        #pragma unroll
        for (int j = 0; j < TN; j++) acc[i][j] = 0.0;

    for (int k0 = 0; k0 < K; k0 += BK) {
        #pragma unroll
        for (int r = 0; r < 2; r++) {
            int f = tid + r * 128;
            int row = f >> 2;
            int seg = f & 3;
            int gRow = blockRow + row;
            float4 v = make_float4(0.f, 0.f, 0.f, 0.f);
            if (gRow < M) v = *(const float4*)(A + (size_t)gRow * lda + k0 + seg * 4);
            As[seg * 4 + 0][row] = v.x;
            As[seg * 4 + 1][row] = v.y;
            As[seg * 4 + 2][row] = v.z;
            As[seg * 4 + 3][row] = v.w;
        }
        #pragma unroll
        for (int e = tid; e < BK * BN / 4; e += 128)
            ((float4*)Bs)[e] = ((const float4*)(B + (size_t)k0 * BN))[e];
        __syncthreads();
        #pragma unroll
        for (int kk = 0; kk < BK; kk++) {
            double a2[TM / 2];
            #pragma unroll
            for (int i = 0; i < TM / 2; i++)
                a2[i] = *(const double*)&As[kk][ty * TM + 2 * i];
            double b2[TN];
            #pragma unroll
            for (int j = 0; j < TN / 2; j++) {
                float2 t2 = *(const float2*)&Bs[kk][tx * TN + 2 * j];
                b2[2 * j + 0] = pack2(t2.x, t2.x);
                b2[2 * j + 1] = pack2(t2.y, t2.y);
            }
            #pragma unroll
            for (int i = 0; i < TM / 2; i++)
                #pragma unroll
                for (int j = 0; j < TN; j++) fma2(acc[i][j], a2[i], b2[j]);
        }
        __syncthreads();
    }

    #pragma unroll
    for (int i = 0; i < TM / 2; i++) {
        float2 col[TN];
        #pragma unroll
        for (int j = 0; j < TN; j++) col[j] = unpack2(acc[i][j]);
        #pragma unroll
        for (int half = 0; half < 2; half++) {
            int gRow = blockRow + ty * TM + 2 * i + half;
            if (gRow >= M) continue;
            float v[TN];
            #pragma unroll
            for (int j = 0; j < TN; j++) {
                float t = (half ? col[j].y : col[j].x) + bias[tx * TN + j];
                v[j] = RELU ? fmaxf(t, 0.f) : t;
            }
            if (WF32) {
                float* crow = C + (size_t)gRow * ldc + tx * TN;
                #pragma unroll
                for (int j = 0; j < TN / 2; j++)
                    *(float2*)(crow + 2 * j) = make_float2(v[2 * j], v[2 * j + 1]);
                if (C2) {
                    float* c2row = C2 + (size_t)gRow * ldc + tx * TN;
                    #pragma unroll
                    for (int j = 0; j < TN / 2; j++)
                        *(float2*)(c2row + 2 * j) = make_float2(v[2 * j], v[2 * j + 1]);
                }
            }
            if (WHALF && TN == 6) {
                uint32_t* hrow = Chalf + (size_t)gRow * HWORDS + tx * 3;
                #pragma unroll
                for (int j = 0; j < 3; j++) {
                    __half2 hv = __float22half2_rn(make_float2(v[2 * j], v[2 * j + 1]));
                    hrow[j] = *(uint32_t*)&hv;
                }
            }
        }
    }
}

// ---------------- per-node aggregation over fp16 h (identical to R7) ----------------
__global__ void aggregate_kernel(const uint32_t* __restrict__ hh, int layer,
                                 float* __restrict__ agg) {
    int warp = (blockIdx.x * blockDim.x + threadIdx.x) >> 5;
    int lane = threadIdx.x & 31;
    if (warp >= N_NODES) return;
    int beg = g_offsets[warp];
    int end = g_offsets[warp + 1];
    bool lo = lane < 16;

    float2 A0 = {0.f, 0.f}, B0 = {0.f, 0.f};
    float2 A1 = {0.f, 0.f}, B1 = {0.f, 0.f};
    int j = beg;
    for (; j + 3 < end; j += 4) {
        int s0 = g_src_sorted[j],     s1 = g_src_sorted[j + 1];
        int s2 = g_src_sorted[j + 2], s3 = g_src_sorted[j + 3];
        float2 w0 = g_ews[(size_t)j * NUM_LAYERS + layer];
        float2 w1 = g_ews[(size_t)(j + 1) * NUM_LAYERS + layer];
        float2 w2 = g_ews[(size_t)(j + 2) * NUM_LAYERS + layer];
        float2 w3 = g_ews[(size_t)(j + 3) * NUM_LAYERS + layer];
        const uint32_t* r0 = hh + (size_t)s0 * HWORDS;
        const uint32_t* r1 = hh + (size_t)s1 * HWORDS;
        const uint32_t* r2 = hh + (size_t)s2 * HWORDS;
        const uint32_t* r3 = hh + (size_t)s3 * HWORDS;
        uint32_t u00 = r0[lane], u10 = r1[lane], u20 = r2[lane], u30 = r3[lane];
        uint32_t u01 = lo ? r0[32 + lane] : 0;
        uint32_t u11 = lo ? r1[32 + lane] : 0;
        uint32_t u21 = lo ? r2[32 + lane] : 0;
        uint32_t u31 = lo ? r3[32 + lane] : 0;
        float2 x;
        x = __half22float2(*(__half2*)&u00);
        A0.x += w0.x * x.x; A0.y += w0.x * x.y; B0.x += w0.y * x.x; B0.y += w0.y * x.y;
        x = __half22float2(*(__half2*)&u10);
        A0.x += w1.x * x.x; A0.y += w1.x * x.y; B0.x += w1.y * x.x; B0.y += w1.y * x.y;
        x = __half22float2(*(__half2*)&u20);
        A0.x += w2.x * x.x; A0.y += w2.x * x.y; B0.x += w2.y * x.x; B0.y += w2.y * x.y;
        x = __half22float2(*(__half2*)&u30);
        A0.x += w3.x * x.x; A0.y += w3.x * x.y; B0.x += w3.y * x.x; B0.y += w3.y * x.y;
        x = __half22float2(*(__half2*)&u01);
        A1.x += w0.x * x.x; A1.y += w0.x * x.y; B1.x += w0.y * x.x; B1.y += w0.y * x.y;
        x = __half22float2(*(__half2*)&u11);
        A1.x += w1.x * x.x; A1.y += w1.x * x.y; B1.x += w1.y * x.x; B1.y += w1.y * x.y;
        x = __half22float2(*(__half2*)&u21);
        A1.x += w2.x * x.x; A1.y += w2.x * x.y; B1.x += w2.y * x.x; B1.y += w2.y * x.y;
        x = __half22float2(*(__half2*)&u31);
        A1.x += w3.x * x.x; A1.y += w3.x * x.y; B1.x += w3.y * x.x; B1.y += w3.y * x.y;
    }
    for (; j < end; j++) {
        int s = g_src_sorted[j];
        float2 w = g_ews[(size_t)j * NUM_LAYERS + layer];
        const uint32_t* r = hh + (size_t)s * HWORDS;
        uint32_t u0 = r[lane];
        uint32_t u1 = lo ? r[32 + lane] : 0;
        float2 x = __half22float2(*(__half2*)&u0);
        A0.x += w.x * x.x; A0.y += w.x * x.y; B0.x += w.y * x.x; B0.y += w.y * x.y;
        x = __half22float2(*(__half2*)&u1);
        A1.x += w.x * x.x; A1.y += w.x * x.y; B1.x += w.y * x.x; B1.y += w.y * x.y;
    }
    float* o = agg + (size_t)warp * (2 * H_DIM);
    *(float2*)(o + 2 * lane)       = A0;
    *(float2*)(o + 96 + 2 * lane)  = B0;
    if (lo) {
        *(float2*)(o + 64 + 2 * lane)  = A1;
        *(float2*)(o + 160 + 2 * lane) = B1;
    }
}

// ---------------- launch ----------------
extern "C" void kernel_launch(void* const* d_in, const int* in_sizes, int n_in,
                              void* d_out, int out_size) {
    const float* x       = (const float*)d_in[0];
    const int*   eidx    = (const int*)d_in[1];
    const float* enc_w   = (const float*)d_in[2];
    const float* enc_b   = (const float*)d_in[3];
    const float* dec_w   = (const float*)d_in[4];
    const float* dec_b   = (const float*)d_in[5];
    const float* conv_W  = (const float*)d_in[6];
    const float* conv_ew = (const float*)d_in[7];
    float* out = (float*)d_out;

    const int* src = eidx;
    const int* dst = eidx + E_EDGES;

    void *p_hfin, *p_hh, *p_agg, *p_zb, *p_counts;
    cudaGetSymbolAddress(&p_hfin, g_hfin);
    cudaGetSymbolAddress(&p_hh, g_hhalf);
    cudaGetSymbolAddress(&p_agg, g_agg);
    cudaGetSymbolAddress(&p_zb, g_zero_bias);
    cudaGetSymbolAddress(&p_counts, g_counts);
    float* hfin = (float*)p_hfin;
    uint32_t* hh = (uint32_t*)p_hh;
    float* agg = (float*)p_agg;
    const float* zb = (const float*)p_zb;

    // one-time host-side stream/event resources (no device memory involved)
    static cudaStream_t sB = nullptr;
    static cudaEvent_t evStart, evEnc, evScat, evB;
    if (!sB) {
        cudaStreamCreateWithFlags(&sB, cudaStreamNonBlocking);
        cudaEventCreateWithFlags(&evStart, cudaEventDisableTiming);
        cudaEventCreateWithFlags(&evEnc, cudaEventDisableTiming);
        cudaEventCreateWithFlags(&evScat, cudaEventDisableTiming);
        cudaEventCreateWithFlags(&evB, cudaEventDisableTiming);
    }

    int gemmGrid = (N_NODES + 63) / 64;

    // ---- fork: encoder GEMM on side stream (independent of CSR build) ----
    cudaEventRecord(evStart, 0);
    cudaStreamWaitEvent(sB, evStart, 0);
    gemm_kernel<6, true, false, true><<<gemmGrid, 128, 0, sB>>>(
        x, enc_w, enc_b, nullptr, hh, nullptr, N_NODES, IN_DIM, IN_DIM, H_DIM);
    cudaEventRecord(evEnc, sB);

    // ---- main stream: CSR build ----
    cudaMemsetAsync(p_counts, 0, N_NODES * sizeof(int), 0);
    hist_kernel<<<(E_EDGES + 255) / 256, 256>>>(dst);
    block_scan_kernel<<<NB_SCAN, 1024>>>();
    add_base_kernel<<<(N_NODES + 256) / 256, 256>>>();
    scatter_light_kernel<<<(E_EDGES + 255) / 256, 256>>>(src, dst, conv_ew);
    cudaEventRecord(evScat, 0);

    // side stream: layers 1..3 weights (overlaps agg0/gemm0 on main stream)
    cudaStreamWaitEvent(sB, evScat, 0);
    ews_rest_kernel<<<(E_EDGES + 255) / 256, 256, 0, sB>>>(conv_ew);
    cudaEventRecord(evB, sB);

    // ---- layers (main stream) ----
    cudaStreamWaitEvent(0, evEnc, 0);
    // layer 0 (only needs layer-0 weights from scatter_light)
    aggregate_kernel<<<(N_NODES * 32 + 255) / 256, 256>>>(hh, 0, agg);
    gemm_kernel<6, true, false, true><<<gemmGrid, 128>>>(
        agg, conv_W, zb, nullptr, hh, nullptr, N_NODES, 2 * H_DIM, 2 * H_DIM, H_DIM);
    cudaStreamWaitEvent(0, evB, 0);
    // layers 1..2: fp16 h only
    for (int l = 1; l < NUM_LAYERS - 1; l++) {
        aggregate_kernel<<<(N_NODES * 32 + 255) / 256, 256>>>(hh, l, agg);
        gemm_kernel<6, true, false, true><<<gemmGrid, 128>>>(
            agg, conv_W + (size_t)l * 2 * H_DIM * H_DIM, zb, nullptr, hh, nullptr,
            N_NODES, 2 * H_DIM, 2 * H_DIM, H_DIM);
    }
    // layer 3: fp32 h for decoder + duplicate into out tail
    aggregate_kernel<<<(N_NODES * 32 + 255) / 256, 256>>>(hh, NUM_LAYERS - 1, agg);
    gemm_kernel<6, true, true, false><<<gemmGrid, 128>>>(
        agg, conv_W + (size_t)(NUM_LAYERS - 1) * 2 * H_DIM * H_DIM, zb, hfin, nullptr,
        out + (size_t)N_NODES * OUT_DIM, N_NODES, 2 * H_DIM, 2 * H_DIM, H_DIM);

    // decoder
    gemm_kernel<4, false, true, false><<<gemmGrid, 128>>>(
        hfin, dec_w, dec_b, out, nullptr, nullptr, N_NODES, H_DIM, H_DIM, OUT_DIM);
    (void)in_sizes; (void)n_in; (void)out_size;
}

// round 10
// speedup vs baseline: 1.0186x; 1.0186x over previous
#include <cuda_runtime.h>
#include <cuda_fp16.h>
#include <cstdint>

#define N_NODES 50000
#define E_EDGES 800000
#define IN_DIM  128
#define H_DIM   96
#define OUT_DIM 64
#define NUM_LAYERS 4
#define NB_SCAN ((N_NODES + 1023) / 1024)
#define HWORDS  48   // 96 channels as half2 words

// ---------------- static device scratch ----------------
__device__ float    g_hfin[N_NODES * H_DIM];                 // final-layer fp32 h
__device__ uint32_t g_hhalf[(size_t)N_NODES * HWORDS];       // h as half2 words
__device__ float    g_agg[(size_t)N_NODES * 2 * H_DIM];
__device__ int      g_counts[N_NODES];
__device__ int      g_offsets[N_NODES + 1];
__device__ int      g_cursor[N_NODES];
__device__ int      g_src_sorted[E_EDGES];
__device__ float2   g_ews[(size_t)E_EDGES * NUM_LAYERS];
__device__ int      g_bsum[NB_SCAN + 1];
__device__ float    g_zero_bias[H_DIM];

// ---------------- f32x2 packed helpers ----------------
__device__ __forceinline__ double pack2(float lo, float hi) {
    double d;
    asm("mov.b64 %0, {%1, %2};" : "=d"(d) : "f"(lo), "f"(hi));
    return d;
}
__device__ __forceinline__ void fma2(double& acc, double a, double b) {
    asm("fma.rn.f32x2 %0, %1, %2, %0;" : "+d"(acc) : "d"(a), "d"(b));
}
__device__ __forceinline__ float2 unpack2(double d) {
    float lo, hi;
    asm("mov.b64 {%0, %1}, %2;" : "=f"(lo), "=f"(hi) : "d"(d));
    return make_float2(lo, hi);
}

// ---------------- CSR build ----------------
__global__ void hist_kernel(const int* __restrict__ dst) {
    int e = blockIdx.x * blockDim.x + threadIdx.x;
    if (e < E_EDGES) atomicAdd(&g_counts[dst[e]], 1);
}

__global__ void block_scan_kernel() {
    __shared__ int sh[1024];
    int t = threadIdx.x;
    int i = blockIdx.x * 1024 + t;
    int v = (i < N_NODES) ? g_counts[i] : 0;
    sh[t] = v;
    __syncthreads();
    #pragma unroll
    for (int off = 1; off < 1024; off <<= 1) {
        int x = (t >= off) ? sh[t - off] : 0;
        __syncthreads();
        sh[t] += x;
        __syncthreads();
    }
    if (i < N_NODES) g_offsets[i] = sh[t] - v;
    if (t == 1023) g_bsum[blockIdx.x] = sh[1023];
}

__global__ void add_base_kernel() {
    __shared__ int pref[NB_SCAN + 1];
    if (threadIdx.x == 0) {
        int run = 0;
        #pragma unroll
        for (int i = 0; i < NB_SCAN; i++) { pref[i] = run; run += g_bsum[i]; }
        pref[NB_SCAN] = run;
    }
    __syncthreads();
    int i = blockIdx.x * blockDim.x + threadIdx.x;
    if (i < N_NODES) {
        int o = g_offsets[i] + pref[i >> 10];
        g_offsets[i] = o;
        g_cursor[i] = o;
    }
    if (i == N_NODES) g_offsets[N_NODES] = pref[NB_SCAN];
}

__global__ void scatter_kernel(const int* __restrict__ src,
                               const int* __restrict__ dst,
                               const float* __restrict__ conv_ew) {
    int e = blockIdx.x * blockDim.x + threadIdx.x;
    if (e >= E_EDGES) return;
    int d = dst[e];
    int pos = atomicAdd(&g_cursor[d], 1);
    g_src_sorted[pos] = src[e];
    #pragma unroll
    for (int l = 0; l < NUM_LAYERS; l++) {
        float w0 = conv_ew[(size_t)(l * 2 + 0) * E_EDGES + e];
        float w1 = conv_ew[(size_t)(l * 2 + 1) * E_EDGES + e];
        g_ews[(size_t)pos * NUM_LAYERS + l] = make_float2(w0, w1);
    }
}

// ---------------- register-tiled fp32 GEMM, packed f32x2 FMA ----------------
template <int TN, bool RELU, bool WF32, bool WHALF>
__global__ void __launch_bounds__(128)
gemm_kernel(const float* __restrict__ A, const float* __restrict__ B,
            const float* __restrict__ bias, float* __restrict__ C,
            uint32_t* __restrict__ Chalf, float* __restrict__ C2,
            int M, int K, int lda, int ldc) {
    constexpr int BN = TN * 16;
    constexpr int BM = 64;
    constexpr int BK = 16;
    constexpr int TM = 8;
    __shared__ float As[BK][BM + 4];
    __shared__ float Bs[BK][BN];

    int tid = threadIdx.x;
    int tx = tid & 15;
    int ty = tid >> 4;
    int blockRow = blockIdx.x * BM;

    double acc[TM / 2][TN];
    #pragma unroll
    for (int i = 0; i < TM / 2; i++)
        #pragma unroll
        for (int j = 0; j < TN; j++) acc[i][j] = 0.0;

    for (int k0 = 0; k0 < K; k0 += BK) {
        #pragma unroll
        for (int r = 0; r < 2; r++) {
            int f = tid + r * 128;
            int row = f >> 2;
            int seg = f & 3;
            int gRow = blockRow + row;
            float4 v = make_float4(0.f, 0.f, 0.f, 0.f);
            if (gRow < M) v = *(const float4*)(A + (size_t)gRow * lda + k0 + seg * 4);
            As[seg * 4 + 0][row] = v.x;
            As[seg * 4 + 1][row] = v.y;
            As[seg * 4 + 2][row] = v.z;
            As[seg * 4 + 3][row] = v.w;
        }
        #pragma unroll
        for (int e = tid; e < BK * BN / 4; e += 128)
            ((float4*)Bs)[e] = ((const float4*)(B + (size_t)k0 * BN))[e];
        __syncthreads();
        #pragma unroll
        for (int kk = 0; kk < BK; kk++) {
            double a2[TM / 2];
            #pragma unroll
            for (int i = 0; i < TM / 2; i++)
                a2[i] = *(const double*)&As[kk][ty * TM + 2 * i];
            double b2[TN];
            #pragma unroll
            for (int j = 0; j < TN / 2; j++) {
                float2 t2 = *(const float2*)&Bs[kk][tx * TN + 2 * j];
                b2[2 * j + 0] = pack2(t2.x, t2.x);
                b2[2 * j + 1] = pack2(t2.y, t2.y);
            }
            #pragma unroll
            for (int i = 0; i < TM / 2; i++)
                #pragma unroll
                for (int j = 0; j < TN; j++) fma2(acc[i][j], a2[i], b2[j]);
        }
        __syncthreads();
    }

    #pragma unroll
    for (int i = 0; i < TM / 2; i++) {
        float2 col[TN];
        #pragma unroll
        for (int j = 0; j < TN; j++) col[j] = unpack2(acc[i][j]);
        #pragma unroll
        for (int half = 0; half < 2; half++) {
            int gRow = blockRow + ty * TM + 2 * i + half;
            if (gRow >= M) continue;
            float v[TN];
            #pragma unroll
            for (int j = 0; j < TN; j++) {
                float t = (half ? col[j].y : col[j].x) + bias[tx * TN + j];
                v[j] = RELU ? fmaxf(t, 0.f) : t;
            }
            if (WF32) {
                float* crow = C + (size_t)gRow * ldc + tx * TN;
                #pragma unroll
                for (int j = 0; j < TN / 2; j++)
                    *(float2*)(crow + 2 * j) = make_float2(v[2 * j], v[2 * j + 1]);
                if (C2) {
                    float* c2row = C2 + (size_t)gRow * ldc + tx * TN;
                    #pragma unroll
                    for (int j = 0; j < TN / 2; j++)
                        *(float2*)(c2row + 2 * j) = make_float2(v[2 * j], v[2 * j + 1]);
                }
            }
            if (WHALF && TN == 6) {
                uint32_t* hrow = Chalf + (size_t)gRow * HWORDS + tx * 3;
                #pragma unroll
                for (int j = 0; j < 3; j++) {
                    __half2 hv = __float22half2_rn(make_float2(v[2 * j], v[2 * j + 1]));
                    hrow[j] = *(uint32_t*)&hv;
                }
            }
        }
    }
}

// ---------------- per-node aggregation over fp16 h (warp per node, 8-edge unroll) ----------------
// lane covers channels {2*lane, 2*lane+1}; lanes 0-15 additionally {64+2*lane, 65+2*lane}.
__global__ void aggregate_kernel(const uint32_t* __restrict__ hh, int layer,
                                 float* __restrict__ agg) {
    int warp = (blockIdx.x * blockDim.x + threadIdx.x) >> 5;
    int lane = threadIdx.x & 31;
    if (warp >= N_NODES) return;
    int beg = g_offsets[warp];
    int end = g_offsets[warp + 1];
    bool lo = lane < 16;

    float2 A0 = {0.f, 0.f}, B0 = {0.f, 0.f};
    float2 A1 = {0.f, 0.f}, B1 = {0.f, 0.f};
    int j = beg;

    // 8-edge unrolled main loop: batch indices+weights, then 8 independent h loads, then math
    for (; j + 7 < end; j += 8) {
        int s[8];
        float2 w[8];
        #pragma unroll
        for (int q = 0; q < 8; q++) {
            s[q] = g_src_sorted[j + q];
            w[q] = g_ews[(size_t)(j + q) * NUM_LAYERS + layer];
        }
        uint32_t ua[8], ub[8];
        #pragma unroll
        for (int q = 0; q < 8; q++) {
            const uint32_t* r = hh + (size_t)s[q] * HWORDS;
            ua[q] = r[lane];
            ub[q] = lo ? r[32 + lane] : 0;
        }
        #pragma unroll
        for (int q = 0; q < 8; q++) {
            float2 x = __half22float2(*(__half2*)&ua[q]);
            A0.x += w[q].x * x.x; A0.y += w[q].x * x.y;
            B0.x += w[q].y * x.x; B0.y += w[q].y * x.y;
            x = __half22float2(*(__half2*)&ub[q]);
            A1.x += w[q].x * x.x; A1.y += w[q].x * x.y;
            B1.x += w[q].y * x.x; B1.y += w[q].y * x.y;
        }
    }
    // 4-edge step
    for (; j + 3 < end; j += 4) {
        int s[4];
        float2 w[4];
        #pragma unroll
        for (int q = 0; q < 4; q++) {
            s[q] = g_src_sorted[j + q];
            w[q] = g_ews[(size_t)(j + q) * NUM_LAYERS + layer];
        }
        uint32_t ua[4], ub[4];
        #pragma unroll
        for (int q = 0; q < 4; q++) {
            const uint32_t* r = hh + (size_t)s[q] * HWORDS;
            ua[q] = r[lane];
            ub[q] = lo ? r[32 + lane] : 0;
        }
        #pragma unroll
        for (int q = 0; q < 4; q++) {
            float2 x = __half22float2(*(__half2*)&ua[q]);
            A0.x += w[q].x * x.x; A0.y += w[q].x * x.y;
            B0.x += w[q].y * x.x; B0.y += w[q].y * x.y;
            x = __half22float2(*(__half2*)&ub[q]);
            A1.x += w[q].x * x.x; A1.y += w[q].x * x.y;
            B1.x += w[q].y * x.x; B1.y += w[q].y * x.y;
        }
    }
    for (; j < end; j++) {
        int s = g_src_sorted[j];
        float2 w = g_ews[(size_t)j * NUM_LAYERS + layer];
        const uint32_t* r = hh + (size_t)s * HWORDS;
        uint32_t u0 = r[lane];
        uint32_t u1 = lo ? r[32 + lane] : 0;
        float2 x = __half22float2(*(__half2*)&u0);
        A0.x += w.x * x.x; A0.y += w.x * x.y; B0.x += w.y * x.x; B0.y += w.y * x.y;
        x = __half22float2(*(__half2*)&u1);
        A1.x += w.x * x.x; A1.y += w.x * x.y; B1.x += w.y * x.x; B1.y += w.y * x.y;
    }
    float* o = agg + (size_t)warp * (2 * H_DIM);
    *(float2*)(o + 2 * lane)       = A0;
    *(float2*)(o + 96 + 2 * lane)  = B0;
    if (lo) {
        *(float2*)(o + 64 + 2 * lane)  = A1;
        *(float2*)(o + 160 + 2 * lane) = B1;
    }
}

// ---------------- launch (single stream) ----------------
extern "C" void kernel_launch(void* const* d_in, const int* in_sizes, int n_in,
                              void* d_out, int out_size) {
    const float* x       = (const float*)d_in[0];
    const int*   eidx    = (const int*)d_in[1];
    const float* enc_w   = (const float*)d_in[2];
    const float* enc_b   = (const float*)d_in[3];
    const float* dec_w   = (const float*)d_in[4];
    const float* dec_b   = (const float*)d_in[5];
    const float* conv_W  = (const float*)d_in[6];
    const float* conv_ew = (const float*)d_in[7];
    float* out = (float*)d_out;

    const int* src = eidx;
    const int* dst = eidx + E_EDGES;

    void *p_hfin, *p_hh, *p_agg, *p_zb, *p_counts;
    cudaGetSymbolAddress(&p_hfin, g_hfin);
    cudaGetSymbolAddress(&p_hh, g_hhalf);
    cudaGetSymbolAddress(&p_agg, g_agg);
    cudaGetSymbolAddress(&p_zb, g_zero_bias);
    cudaGetSymbolAddress(&p_counts, g_counts);
    float* hfin = (float*)p_hfin;
    uint32_t* hh = (uint32_t*)p_hh;
    float* agg = (float*)p_agg;
    const float* zb = (const float*)p_zb;

    // CSR build
    cudaMemsetAsync(p_counts, 0, N_NODES * sizeof(int));
    hist_kernel<<<(E_EDGES + 255) / 256, 256>>>(dst);
    block_scan_kernel<<<NB_SCAN, 1024>>>();
    add_base_kernel<<<(N_NODES + 256) / 256, 256>>>();
    scatter_kernel<<<(E_EDGES + 255) / 256, 256>>>(src, dst, conv_ew);

    int gemmGrid = (N_NODES + 63) / 64;

    // encoder: fp16 h only
    gemm_kernel<6, true, false, true><<<gemmGrid, 128>>>(
        x, enc_w, enc_b, nullptr, hh, nullptr, N_NODES, IN_DIM, IN_DIM, H_DIM);

    // layers 0..2: fp16 h only
    for (int l = 0; l < NUM_LAYERS - 1; l++) {
        aggregate_kernel<<<(N_NODES * 32 + 255) / 256, 256>>>(hh, l, agg);
        gemm_kernel<6, true, false, true><<<gemmGrid, 128>>>(
            agg, conv_W + (size_t)l * 2 * H_DIM * H_DIM, zb, nullptr, hh, nullptr,
            N_NODES, 2 * H_DIM, 2 * H_DIM, H_DIM);
    }
    // layer 3: fp32 h for decoder + duplicate into out tail
    aggregate_kernel<<<(N_NODES * 32 + 255) / 256, 256>>>(hh, NUM_LAYERS - 1, agg);
    gemm_kernel<6, true, true, false><<<gemmGrid, 128>>>(
        agg, conv_W + (size_t)(NUM_LAYERS - 1) * 2 * H_DIM * H_DIM, zb, hfin, nullptr,
        out + (size_t)N_NODES * OUT_DIM, N_NODES, 2 * H_DIM, 2 * H_DIM, H_DIM);

    // decoder
    gemm_kernel<4, false, true, false><<<gemmGrid, 128>>>(
        hfin, dec_w, dec_b, out, nullptr, nullptr, N_NODES, H_DIM, H_DIM, OUT_DIM);
    (void)in_sizes; (void)n_in; (void)out_size;
}

// round 11
// speedup vs baseline: 1.2261x; 1.2037x over previous
#include <cuda_runtime.h>
#include <cuda_fp16.h>
#include <cstdint>

#define N_NODES 50000
#define E_EDGES 800000
#define IN_DIM  128
#define H_DIM   96
#define OUT_DIM 64
#define NUM_LAYERS 4
#define NB_SCAN ((N_NODES + 1023) / 1024)
#define HWORDS  48   // 96 channels as half2 words
#define AGGW    96   // 192 channels as half2 words

// ---------------- static device scratch ----------------
__device__ float    g_hfin[N_NODES * H_DIM];                 // final-layer fp32 h
__device__ uint32_t g_hhalf[(size_t)N_NODES * HWORDS];       // h as half2 words
__device__ float    g_agg[(size_t)N_NODES * 2 * H_DIM];      // fp32 agg (layer 3 only)
__device__ uint32_t g_aggh[(size_t)N_NODES * AGGW];          // fp16 agg (layers 0-2)
__device__ uint32_t g_xh[(size_t)N_NODES * IN_DIM / 2];      // x as half2
__device__ uint32_t g_whalf[(12288 + 3 * 18432) / 2];        // enc_w + conv_W[0..2] fp16
__device__ int      g_counts[N_NODES];
__device__ int      g_offsets[N_NODES + 1];
__device__ int      g_cursor[N_NODES];
__device__ int      g_src_sorted[E_EDGES];
__device__ float2   g_ews[(size_t)E_EDGES * NUM_LAYERS];
__device__ int      g_bsum[NB_SCAN + 1];
__device__ float    g_zero_bias[H_DIM];

// ---------------- helpers ----------------
__device__ __forceinline__ double pack2(float lo, float hi) {
    double d;
    asm("mov.b64 %0, {%1, %2};" : "=d"(d) : "f"(lo), "f"(hi));
    return d;
}
__device__ __forceinline__ void fma2(double& acc, double a, double b) {
    asm("fma.rn.f32x2 %0, %1, %2, %0;" : "+d"(acc) : "d"(a), "d"(b));
}
__device__ __forceinline__ float2 unpack2(double d) {
    float lo, hi;
    asm("mov.b64 {%0, %1}, %2;" : "=f"(lo), "=f"(hi) : "d"(d));
    return make_float2(lo, hi);
}
__device__ __forceinline__ uint32_t smem_u32(const void* p) {
    uint32_t a;
    asm("{ .reg .u64 t; cvta.to.shared.u64 t, %1; cvt.u32.u64 %0, t; }" : "=r"(a) : "l"(p));
    return a;
}
__device__ __forceinline__ void ldmatrix_x4(uint32_t* r, uint32_t addr) {
    asm volatile("ldmatrix.sync.aligned.m8n8.x4.shared.b16 {%0,%1,%2,%3}, [%4];"
                 : "=r"(r[0]), "=r"(r[1]), "=r"(r[2]), "=r"(r[3]) : "r"(addr));
}
__device__ __forceinline__ void ldmatrix_x4_t(uint32_t* r, uint32_t addr) {
    asm volatile("ldmatrix.sync.aligned.m8n8.x4.trans.shared.b16 {%0,%1,%2,%3}, [%4];"
                 : "=r"(r[0]), "=r"(r[1]), "=r"(r[2]), "=r"(r[3]) : "r"(addr));
}
__device__ __forceinline__ void mma16816(float* c, const uint32_t* a, const uint32_t* b) {
    asm volatile("mma.sync.aligned.m16n8k16.row.col.f32.f16.f16.f32 "
                 "{%0,%1,%2,%3},{%4,%5,%6,%7},{%8,%9},{%0,%1,%2,%3};"
                 : "+f"(c[0]), "+f"(c[1]), "+f"(c[2]), "+f"(c[3])
                 : "r"(a[0]), "r"(a[1]), "r"(a[2]), "r"(a[3]), "r"(b[0]), "r"(b[1]));
}

// ---------------- CSR build ----------------
__global__ void hist_kernel(const int* __restrict__ dst) {
    int e = blockIdx.x * blockDim.x + threadIdx.x;
    if (e < E_EDGES) atomicAdd(&g_counts[dst[e]], 1);
}

__global__ void block_scan_kernel() {
    __shared__ int sh[1024];
    int t = threadIdx.x;
    int i = blockIdx.x * 1024 + t;
    int v = (i < N_NODES) ? g_counts[i] : 0;
    sh[t] = v;
    __syncthreads();
    #pragma unroll
    for (int off = 1; off < 1024; off <<= 1) {
        int x = (t >= off) ? sh[t - off] : 0;
        __syncthreads();
        sh[t] += x;
        __syncthreads();
    }
    if (i < N_NODES) g_offsets[i] = sh[t] - v;
    if (t == 1023) g_bsum[blockIdx.x] = sh[1023];
}

__global__ void add_base_kernel() {
    __shared__ int pref[NB_SCAN + 1];
    if (threadIdx.x == 0) {
        int run = 0;
        #pragma unroll
        for (int i = 0; i < NB_SCAN; i++) { pref[i] = run; run += g_bsum[i]; }
        pref[NB_SCAN] = run;
    }
    __syncthreads();
    int i = blockIdx.x * blockDim.x + threadIdx.x;
    if (i < N_NODES) {
        int o = g_offsets[i] + pref[i >> 10];
        g_offsets[i] = o;
        g_cursor[i] = o;
    }
    if (i == N_NODES) g_offsets[N_NODES] = pref[NB_SCAN];
}

__global__ void scatter_kernel(const int* __restrict__ src,
                               const int* __restrict__ dst,
                               const float* __restrict__ conv_ew) {
    int e = blockIdx.x * blockDim.x + threadIdx.x;
    if (e >= E_EDGES) return;
    int d = dst[e];
    int pos = atomicAdd(&g_cursor[d], 1);
    g_src_sorted[pos] = src[e];
    #pragma unroll
    for (int l = 0; l < NUM_LAYERS; l++) {
        float w0 = conv_ew[(size_t)(l * 2 + 0) * E_EDGES + e];
        float w1 = conv_ew[(size_t)(l * 2 + 1) * E_EDGES + e];
        g_ews[(size_t)pos * NUM_LAYERS + l] = make_float2(w0, w1);
    }
}

// ---------------- fp16 prep ----------------
__global__ void wprep_kernel(const float* __restrict__ enc_w,
                             const float* __restrict__ conv_W) {
    int i = blockIdx.x * blockDim.x + threadIdx.x;
    const int total = (12288 + 3 * 18432) / 2;
    if (i >= total) return;
    int off = i * 2;
    float2 v = (off < 12288) ? *(const float2*)(enc_w + off)
                             : *(const float2*)(conv_W + (off - 12288));
    __half2 h = __float22half2_rn(v);
    g_whalf[i] = *(uint32_t*)&h;
}

__global__ void xprep_kernel(const float* __restrict__ x) {
    int i = blockIdx.x * blockDim.x + threadIdx.x;
    const int total = N_NODES * IN_DIM / 2;
    if (i >= total) return;
    float2 v = *(const float2*)(x + i * 2);
    __half2 h = __float22half2_rn(v);
    g_xh[i] = *(uint32_t*)&h;
}

// ---------------- HMMA GEMM (fp16 in, fp32 acc, relu, fp16 out) ----------------
// C[M x 96] = relu(A[M x K] @ W[K x 96] + bias). BM=64, 4 warps (2M x 2N of 32x48).
template <int K, bool BIAS>
__global__ void __launch_bounds__(128)
mma_gemm(const __half* __restrict__ Ag, const __half* __restrict__ Wh,
         const float* __restrict__ bias, uint32_t* __restrict__ hh, int M) {
    constexpr int KPAD = (K == 192) ? 200 : 136;
    constexpr int NPAD = 104;
    extern __shared__ __half sm[];
    __half* As = sm;                 // [64][KPAD]
    __half* Bs = sm + 64 * KPAD;     // [K][NPAD]
    int tid = threadIdx.x, lane = tid & 31, wid = tid >> 5;
    int blockRow = blockIdx.x * 64;

    // load A (guarded), fp16 rows contiguous
    constexpr int ACH = K / 8;
    for (int i = tid; i < 64 * ACH; i += 128) {
        int row = i / ACH, c = i % ACH;
        int gRow = blockRow + row;
        uint4 v = make_uint4(0, 0, 0, 0);
        if (gRow < M) v = ((const uint4*)(Ag + (size_t)gRow * K))[c];
        ((uint4*)(As + row * KPAD))[c] = v;
    }
    // load full W
    for (int i = tid; i < K * 12; i += 128) {
        int row = i / 12, c = i % 12;
        ((uint4*)(Bs + row * NPAD))[c] = ((const uint4*)(Wh + (size_t)row * 96))[c];
    }
    __syncthreads();

    int m0w = (wid & 1) * 32;
    int n0w = (wid >> 1) * 48;
    float acc[2][6][4];
    #pragma unroll
    for (int mi = 0; mi < 2; mi++)
        #pragma unroll
        for (int nj = 0; nj < 6; nj++)
            #pragma unroll
            for (int q = 0; q < 4; q++) acc[mi][nj][q] = 0.f;

    uint32_t aBase = smem_u32(As), bBase = smem_u32(Bs);
    #pragma unroll
    for (int ks = 0; ks < K / 16; ks++) {
        int k0 = ks * 16;
        uint32_t a[2][4];
        #pragma unroll
        for (int mi = 0; mi < 2; mi++) {
            uint32_t addr = aBase +
                (((m0w + mi * 16 + (lane & 7) + (lane & 8)) * KPAD + k0 + ((lane >> 4) << 3)) << 1);
            ldmatrix_x4(a[mi], addr);
        }
        uint32_t b[6][2];
        #pragma unroll
        for (int bj = 0; bj < 3; bj++) {
            uint32_t r[4];
            uint32_t addr = bBase +
                (((k0 + (lane & 15)) * NPAD + n0w + bj * 16 + ((lane >> 4) << 3)) << 1);
            ldmatrix_x4_t(r, addr);
            b[2 * bj][0] = r[0]; b[2 * bj][1] = r[1];
            b[2 * bj + 1][0] = r[2]; b[2 * bj + 1][1] = r[3];
        }
        #pragma unroll
        for (int mi = 0; mi < 2; mi++)
            #pragma unroll
            for (int nj = 0; nj < 6; nj++)
                mma16816(acc[mi][nj], a[mi], b[nj]);
    }

    // epilogue: relu(+bias) -> fp16 half2 words (row stride HWORDS)
    #pragma unroll
    for (int mi = 0; mi < 2; mi++) {
        #pragma unroll
        for (int nj = 0; nj < 6; nj++) {
            int col = n0w + nj * 8 + 2 * (lane & 3);
            float bx = 0.f, by = 0.f;
            if (BIAS) { float2 bb = *(const float2*)(bias + col); bx = bb.x; by = bb.y; }
            int r = blockRow + m0w + mi * 16 + (lane >> 2);
            float v0 = fmaxf(acc[mi][nj][0] + bx, 0.f);
            float v1 = fmaxf(acc[mi][nj][1] + by, 0.f);
            float v2 = fmaxf(acc[mi][nj][2] + bx, 0.f);
            float v3 = fmaxf(acc[mi][nj][3] + by, 0.f);
            if (r < M) {
                __half2 h = __float22half2_rn(make_float2(v0, v1));
                hh[(size_t)r * HWORDS + (col >> 1)] = *(uint32_t*)&h;
            }
            if (r + 8 < M) {
                __half2 h = __float22half2_rn(make_float2(v2, v3));
                hh[(size_t)(r + 8) * HWORDS + (col >> 1)] = *(uint32_t*)&h;
            }
        }
    }
}

// ---------------- register-tiled fp32 GEMM, packed f32x2 FMA (layer3 + decoder) ----------------
template <int TN, bool RELU, bool WF32, bool WHALF>
__global__ void __launch_bounds__(128)
gemm_kernel(const float* __restrict__ A, const float* __restrict__ B,
            const float* __restrict__ bias, float* __restrict__ C,
            uint32_t* __restrict__ Chalf, float* __restrict__ C2,
            int M, int K, int lda, int ldc) {
    constexpr int BN = TN * 16;
    constexpr int BM = 64;
    constexpr int BK = 16;
    constexpr int TM = 8;
    __shared__ float As[BK][BM + 4];
    __shared__ float Bs[BK][BN];

    int tid = threadIdx.x;
    int tx = tid & 15;
    int ty = tid >> 4;
    int blockRow = blockIdx.x * BM;

    double acc[TM / 2][TN];
    #pragma unroll
    for (int i = 0; i < TM / 2; i++)
        #pragma unroll
        for (int j = 0; j < TN; j++) acc[i][j] = 0.0;

    for (int k0 = 0; k0 < K; k0 += BK) {
        #pragma unroll
        for (int r = 0; r < 2; r++) {
            int f = tid + r * 128;
            int row = f >> 2;
            int seg = f & 3;
            int gRow = blockRow + row;
            float4 v = make_float4(0.f, 0.f, 0.f, 0.f);
            if (gRow < M) v = *(const float4*)(A + (size_t)gRow * lda + k0 + seg * 4);
            As[seg * 4 + 0][row] = v.x;
            As[seg * 4 + 1][row] = v.y;
            As[seg * 4 + 2][row] = v.z;
            As[seg * 4 + 3][row] = v.w;
        }
        #pragma unroll
        for (int e = tid; e < BK * BN / 4; e += 128)
            ((float4*)Bs)[e] = ((const float4*)(B + (size_t)k0 * BN))[e];
        __syncthreads();
        #pragma unroll
        for (int kk = 0; kk < BK; kk++) {
            double a2[TM / 2];
            #pragma unroll
            for (int i = 0; i < TM / 2; i++)
                a2[i] = *(const double*)&As[kk][ty * TM + 2 * i];
            double b2[TN];
            #pragma unroll
            for (int j = 0; j < TN / 2; j++) {
                float2 t2 = *(const float2*)&Bs[kk][tx * TN + 2 * j];
                b2[2 * j + 0] = pack2(t2.x, t2.x);
                b2[2 * j + 1] = pack2(t2.y, t2.y);
            }
            #pragma unroll
            for (int i = 0; i < TM / 2; i++)
                #pragma unroll
                for (int j = 0; j < TN; j++) fma2(acc[i][j], a2[i], b2[j]);
        }
        __syncthreads();
    }

    #pragma unroll
    for (int i = 0; i < TM / 2; i++) {
        float2 col[TN];
        #pragma unroll
        for (int j = 0; j < TN; j++) col[j] = unpack2(acc[i][j]);
        #pragma unroll
        for (int half = 0; half < 2; half++) {
            int gRow = blockRow + ty * TM + 2 * i + half;
            if (gRow >= M) continue;
            float v[TN];
            #pragma unroll
            for (int j = 0; j < TN; j++) {
                float t = (half ? col[j].y : col[j].x) + bias[tx * TN + j];
                v[j] = RELU ? fmaxf(t, 0.f) : t;
            }
            if (WF32) {
                float* crow = C + (size_t)gRow * ldc + tx * TN;
                #pragma unroll
                for (int j = 0; j < TN / 2; j++)
                    *(float2*)(crow + 2 * j) = make_float2(v[2 * j], v[2 * j + 1]);
                if (C2) {
                    float* c2row = C2 + (size_t)gRow * ldc + tx * TN;
                    #pragma unroll
                    for (int j = 0; j < TN / 2; j++)
                        *(float2*)(c2row + 2 * j) = make_float2(v[2 * j], v[2 * j + 1]);
                }
            }
            if (WHALF && TN == 6) {
                uint32_t* hrow = Chalf + (size_t)gRow * HWORDS + tx * 3;
                #pragma unroll
                for (int j = 0; j < 3; j++) {
                    __half2 hv = __float22half2_rn(make_float2(v[2 * j], v[2 * j + 1]));
                    hrow[j] = *(uint32_t*)&hv;
                }
            }
        }
    }
}

// ---------------- per-node aggregation over fp16 h (warp per node, 8-edge unroll) ----------------
// OUT32: write fp32 agg (layer 3). else: write fp16 agg (layers 0-2).
template <bool OUT32>
__global__ void aggregate_kernel(const uint32_t* __restrict__ hh, int layer,
                                 float* __restrict__ aggf, uint32_t* __restrict__ aggh) {
    int warp = (blockIdx.x * blockDim.x + threadIdx.x) >> 5;
    int lane = threadIdx.x & 31;
    if (warp >= N_NODES) return;
    int beg = g_offsets[warp];
    int end = g_offsets[warp + 1];
    bool lo = lane < 16;

    float2 A0 = {0.f, 0.f}, B0 = {0.f, 0.f};
    float2 A1 = {0.f, 0.f}, B1 = {0.f, 0.f};
    int j = beg;

    for (; j + 7 < end; j += 8) {
        int s[8];
        float2 w[8];
        #pragma unroll
        for (int q = 0; q < 8; q++) {
            s[q] = g_src_sorted[j + q];
            w[q] = g_ews[(size_t)(j + q) * NUM_LAYERS + layer];
        }
        uint32_t ua[8], ub[8];
        #pragma unroll
        for (int q = 0; q < 8; q++) {
            const uint32_t* r = hh + (size_t)s[q] * HWORDS;
            ua[q] = r[lane];
            ub[q] = lo ? r[32 + lane] : 0;
        }
        #pragma unroll
        for (int q = 0; q < 8; q++) {
            float2 x = __half22float2(*(__half2*)&ua[q]);
            A0.x += w[q].x * x.x; A0.y += w[q].x * x.y;
            B0.x += w[q].y * x.x; B0.y += w[q].y * x.y;
            x = __half22float2(*(__half2*)&ub[q]);
            A1.x += w[q].x * x.x; A1.y += w[q].x * x.y;
            B1.x += w[q].y * x.x; B1.y += w[q].y * x.y;
        }
    }
    for (; j + 3 < end; j += 4) {
        int s[4];
        float2 w[4];
        #pragma unroll
        for (int q = 0; q < 4; q++) {
            s[q] = g_src_sorted[j + q];
            w[q] = g_ews[(size_t)(j + q) * NUM_LAYERS + layer];
        }
        uint32_t ua[4], ub[4];
        #pragma unroll
        for (int q = 0; q < 4; q++) {
            const uint32_t* r = hh + (size_t)s[q] * HWORDS;
            ua[q] = r[lane];
            ub[q] = lo ? r[32 + lane] : 0;
        }
        #pragma unroll
        for (int q = 0; q < 4; q++) {
            float2 x = __half22float2(*(__half2*)&ua[q]);
            A0.x += w[q].x * x.x; A0.y += w[q].x * x.y;
            B0.x += w[q].y * x.x; B0.y += w[q].y * x.y;
            x = __half22float2(*(__half2*)&ub[q]);
            A1.x += w[q].x * x.x; A1.y += w[q].x * x.y;
            B1.x += w[q].y * x.x; B1.y += w[q].y * x.y;
        }
    }
    for (; j < end; j++) {
        int s = g_src_sorted[j];
        float2 w = g_ews[(size_t)j * NUM_LAYERS + layer];
        const uint32_t* r = hh + (size_t)s * HWORDS;
        uint32_t u0 = r[lane];
        uint32_t u1 = lo ? r[32 + lane] : 0;
        float2 x = __half22float2(*(__half2*)&u0);
        A0.x += w.x * x.x; A0.y += w.x * x.y; B0.x += w.y * x.x; B0.y += w.y * x.y;
        x = __half22float2(*(__half2*)&u1);
        A1.x += w.x * x.x; A1.y += w.x * x.y; B1.x += w.y * x.x; B1.y += w.y * x.y;
    }
    if (OUT32) {
        float* o = aggf + (size_t)warp * (2 * H_DIM);
        *(float2*)(o + 2 * lane)       = A0;
        *(float2*)(o + 96 + 2 * lane)  = B0;
        if (lo) {
            *(float2*)(o + 64 + 2 * lane)  = A1;
            *(float2*)(o + 160 + 2 * lane) = B1;
        }
    } else {
        uint32_t* o = aggh + (size_t)warp * AGGW;
        __half2 h;
        h = __float22half2_rn(A0); o[lane]      = *(uint32_t*)&h;
        h = __float22half2_rn(B0); o[48 + lane] = *(uint32_t*)&h;
        if (lo) {
            h = __float22half2_rn(A1); o[32 + lane] = *(uint32_t*)&h;
            h = __float22half2_rn(B1); o[80 + lane] = *(uint32_t*)&h;
        }
    }
}

// ---------------- launch (single stream) ----------------
extern "C" void kernel_launch(void* const* d_in, const int* in_sizes, int n_in,
                              void* d_out, int out_size) {
    const float* x       = (const float*)d_in[0];
    const int*   eidx    = (const int*)d_in[1];
    const float* enc_w   = (const float*)d_in[2];
    const float* enc_b   = (const float*)d_in[3];
    const float* dec_w   = (const float*)d_in[4];
    const float* dec_b   = (const float*)d_in[5];
    const float* conv_W  = (const float*)d_in[6];
    const float* conv_ew = (const float*)d_in[7];
    float* out = (float*)d_out;

    const int* src = eidx;
    const int* dst = eidx + E_EDGES;

    void *p_hfin, *p_hh, *p_agg, *p_aggh, *p_zb, *p_counts, *p_wh, *p_xh;
    cudaGetSymbolAddress(&p_hfin, g_hfin);
    cudaGetSymbolAddress(&p_hh, g_hhalf);
    cudaGetSymbolAddress(&p_agg, g_agg);
    cudaGetSymbolAddress(&p_aggh, g_aggh);
    cudaGetSymbolAddress(&p_zb, g_zero_bias);
    cudaGetSymbolAddress(&p_counts, g_counts);
    cudaGetSymbolAddress(&p_wh, g_whalf);
    cudaGetSymbolAddress(&p_xh, g_xh);
    float* hfin = (float*)p_hfin;
    uint32_t* hh = (uint32_t*)p_hh;
    float* agg = (float*)p_agg;
    uint32_t* aggh = (uint32_t*)p_aggh;
    const float* zb = (const float*)p_zb;
    const __half* wh = (const __half*)p_wh;
    const __half* xh = (const __half*)p_xh;

    constexpr int SMEM_CONV = (64 * 200 + 192 * 104) * 2;   // 65536
    constexpr int SMEM_ENC  = (64 * 136 + 128 * 104) * 2;   // 44032
    cudaFuncSetAttribute(mma_gemm<192, false>, cudaFuncAttributeMaxDynamicSharedMemorySize, SMEM_CONV);
    cudaFuncSetAttribute(mma_gemm<128, true>,  cudaFuncAttributeMaxDynamicSharedMemorySize, SMEM_ENC);

    // CSR build + fp16 prep
    cudaMemsetAsync(p_counts, 0, N_NODES * sizeof(int));
    hist_kernel<<<(E_EDGES + 255) / 256, 256>>>(dst);
    block_scan_kernel<<<NB_SCAN, 1024>>>();
    add_base_kernel<<<(N_NODES + 256) / 256, 256>>>();
    scatter_kernel<<<(E_EDGES + 255) / 256, 256>>>(src, dst, conv_ew);
    wprep_kernel<<<((12288 + 3 * 18432) / 2 + 255) / 256, 256>>>(enc_w, conv_W);
    xprep_kernel<<<(N_NODES * IN_DIM / 2 + 255) / 256, 256>>>(x);

    int gemmGrid = (N_NODES + 63) / 64;

    // encoder (HMMA): h = relu(x @ enc_w + enc_b) -> fp16
    mma_gemm<128, true><<<gemmGrid, 128, SMEM_ENC>>>(xh, wh, enc_b, hh, N_NODES);

    // layers 0..2 (HMMA)
    for (int l = 0; l < NUM_LAYERS - 1; l++) {
        aggregate_kernel<false><<<(N_NODES * 32 + 255) / 256, 256>>>(hh, l, nullptr, aggh);
        mma_gemm<192, false><<<gemmGrid, 128, SMEM_CONV>>>(
            (const __half*)aggh, wh + 12288 + l * 18432, nullptr, hh, N_NODES);
    }
    // layer 3 (fp32): h for decoder + duplicate into out tail
    aggregate_kernel<true><<<(N_NODES * 32 + 255) / 256, 256>>>(hh, NUM_LAYERS - 1, agg, nullptr);
    gemm_kernel<6, true, true, false><<<gemmGrid, 128>>>(
        agg, conv_W + (size_t)(NUM_LAYERS - 1) * 2 * H_DIM * H_DIM, zb, hfin, nullptr,
        out + (size_t)N_NODES * OUT_DIM, N_NODES, 2 * H_DIM, 2 * H_DIM, H_DIM);

    // decoder (fp32)
    gemm_kernel<4, false, true, false><<<gemmGrid, 128>>>(
        hfin, dec_w, dec_b, out, nullptr, nullptr, N_NODES, H_DIM, H_DIM, OUT_DIM);
    (void)in_sizes; (void)n_in; (void)out_size;
}

// round 12
// speedup vs baseline: 1.2483x; 1.0181x over previous
#include <cuda_runtime.h>
#include <cuda_fp16.h>
#include <cstdint>

#define N_NODES 50000
#define E_EDGES 800000
#define IN_DIM  128
#define H_DIM   96
#define OUT_DIM 64
#define NUM_LAYERS 4
#define NB_SCAN ((N_NODES + 1023) / 1024)
#define HWORDS  48   // 96 channels as half2 words
#define AGGW    96   // 192 channels as half2 words

// ---------------- static device scratch ----------------
__device__ float    g_hfin[N_NODES * H_DIM];                 // final-layer fp32 h
__device__ uint32_t g_hhalf[(size_t)N_NODES * HWORDS];       // h as half2 words
__device__ float    g_agg[(size_t)N_NODES * 2 * H_DIM];      // fp32 agg (layer 3 only)
__device__ uint32_t g_aggh[(size_t)N_NODES * AGGW];          // fp16 agg (layers 0-2)
__device__ uint32_t g_xh[(size_t)N_NODES * IN_DIM / 2];      // x as half2
__device__ uint32_t g_whalf[(12288 + 3 * 18432) / 2];        // enc_w + conv_W[0..2] fp16
__device__ int      g_counts[N_NODES];
__device__ int      g_offsets[N_NODES + 1];
__device__ int      g_cursor[N_NODES];
__device__ int      g_src_sorted[E_EDGES];
__device__ float2   g_ews[(size_t)E_EDGES * NUM_LAYERS];
__device__ int      g_bsum[NB_SCAN + 1];
__device__ float    g_zero_bias[H_DIM];

// ---------------- helpers ----------------
__device__ __forceinline__ double pack2(float lo, float hi) {
    double d;
    asm("mov.b64 %0, {%1, %2};" : "=d"(d) : "f"(lo), "f"(hi));
    return d;
}
__device__ __forceinline__ void fma2(double& acc, double a, double b) {
    asm("fma.rn.f32x2 %0, %1, %2, %0;" : "+d"(acc) : "d"(a), "d"(b));
}
__device__ __forceinline__ float2 unpack2(double d) {
    float lo, hi;
    asm("mov.b64 {%0, %1}, %2;" : "=f"(lo), "=f"(hi) : "d"(d));
    return make_float2(lo, hi);
}
__device__ __forceinline__ uint32_t smem_u32(const void* p) {
    uint32_t a;
    asm("{ .reg .u64 t; cvta.to.shared.u64 t, %1; cvt.u32.u64 %0, t; }" : "=r"(a) : "l"(p));
    return a;
}
__device__ __forceinline__ void ldmatrix_x4(uint32_t* r, uint32_t addr) {
    asm volatile("ldmatrix.sync.aligned.m8n8.x4.shared.b16 {%0,%1,%2,%3}, [%4];"
                 : "=r"(r[0]), "=r"(r[1]), "=r"(r[2]), "=r"(r[3]) : "r"(addr));
}
__device__ __forceinline__ void ldmatrix_x4_t(uint32_t* r, uint32_t addr) {
    asm volatile("ldmatrix.sync.aligned.m8n8.x4.trans.shared.b16 {%0,%1,%2,%3}, [%4];"
                 : "=r"(r[0]), "=r"(r[1]), "=r"(r[2]), "=r"(r[3]) : "r"(addr));
}
__device__ __forceinline__ void mma16816(float* c, const uint32_t* a, const uint32_t* b) {
    asm volatile("mma.sync.aligned.m16n8k16.row.col.f32.f16.f16.f32 "
                 "{%0,%1,%2,%3},{%4,%5,%6,%7},{%8,%9},{%0,%1,%2,%3};"
                 : "+f"(c[0]), "+f"(c[1]), "+f"(c[2]), "+f"(c[3])
                 : "r"(a[0]), "r"(a[1]), "r"(a[2]), "r"(a[3]), "r"(b[0]), "r"(b[1]));
}

// ---------------- CSR build ----------------
__global__ void hist_kernel(const int* __restrict__ dst) {
    int e = blockIdx.x * blockDim.x + threadIdx.x;
    if (e < E_EDGES) atomicAdd(&g_counts[dst[e]], 1);
}

__global__ void block_scan_kernel() {
    __shared__ int sh[1024];
    int t = threadIdx.x;
    int i = blockIdx.x * 1024 + t;
    int v = (i < N_NODES) ? g_counts[i] : 0;
    sh[t] = v;
    __syncthreads();
    #pragma unroll
    for (int off = 1; off < 1024; off <<= 1) {
        int x = (t >= off) ? sh[t - off] : 0;
        __syncthreads();
        sh[t] += x;
        __syncthreads();
    }
    if (i < N_NODES) g_offsets[i] = sh[t] - v;
    if (t == 1023) g_bsum[blockIdx.x] = sh[1023];
}

__global__ void add_base_kernel() {
    __shared__ int pref[NB_SCAN + 1];
    if (threadIdx.x == 0) {
        int run = 0;
        #pragma unroll
        for (int i = 0; i < NB_SCAN; i++) { pref[i] = run; run += g_bsum[i]; }
        pref[NB_SCAN] = run;
    }
    __syncthreads();
    int i = blockIdx.x * blockDim.x + threadIdx.x;
    if (i < N_NODES) {
        int o = g_offsets[i] + pref[i >> 10];
        g_offsets[i] = o;
        g_cursor[i] = o;
    }
    if (i == N_NODES) g_offsets[N_NODES] = pref[NB_SCAN];
}

__global__ void scatter_kernel(const int* __restrict__ src,
                               const int* __restrict__ dst,
                               const float* __restrict__ conv_ew) {
    int e = blockIdx.x * blockDim.x + threadIdx.x;
    if (e >= E_EDGES) return;
    int d = dst[e];
    int pos = atomicAdd(&g_cursor[d], 1);
    g_src_sorted[pos] = src[e];
    #pragma unroll
    for (int l = 0; l < NUM_LAYERS; l++) {
        float w0 = conv_ew[(size_t)(l * 2 + 0) * E_EDGES + e];
        float w1 = conv_ew[(size_t)(l * 2 + 1) * E_EDGES + e];
        g_ews[(size_t)pos * NUM_LAYERS + l] = make_float2(w0, w1);
    }
}

// ---------------- fp16 prep ----------------
__global__ void wprep_kernel(const float* __restrict__ enc_w,
                             const float* __restrict__ conv_W) {
    int i = blockIdx.x * blockDim.x + threadIdx.x;
    const int total = (12288 + 3 * 18432) / 2;
    if (i >= total) return;
    int off = i * 2;
    float2 v = (off < 12288) ? *(const float2*)(enc_w + off)
                             : *(const float2*)(conv_W + (off - 12288));
    __half2 h = __float22half2_rn(v);
    g_whalf[i] = *(uint32_t*)&h;
}

__global__ void xprep_kernel(const float* __restrict__ x) {
    int i = blockIdx.x * blockDim.x + threadIdx.x;
    const int total = N_NODES * IN_DIM / 2;
    if (i >= total) return;
    float2 v = *(const float2*)(x + i * 2);
    __half2 h = __float22half2_rn(v);
    g_xh[i] = *(uint32_t*)&h;
}

// ---------------- HMMA GEMM (fp16 in, fp32 acc, relu, fp16 out) ----------------
template <int K, bool BIAS>
__global__ void __launch_bounds__(128)
mma_gemm(const __half* __restrict__ Ag, const __half* __restrict__ Wh,
         const float* __restrict__ bias, uint32_t* __restrict__ hh, int M) {
    constexpr int KPAD = (K == 192) ? 200 : 136;
    constexpr int NPAD = 104;
    extern __shared__ __half sm[];
    __half* As = sm;                 // [64][KPAD]
    __half* Bs = sm + 64 * KPAD;     // [K][NPAD]
    int tid = threadIdx.x, lane = tid & 31, wid = tid >> 5;
    int blockRow = blockIdx.x * 64;

    constexpr int ACH = K / 8;
    for (int i = tid; i < 64 * ACH; i += 128) {
        int row = i / ACH, c = i % ACH;
        int gRow = blockRow + row;
        uint4 v = make_uint4(0, 0, 0, 0);
        if (gRow < M) v = ((const uint4*)(Ag + (size_t)gRow * K))[c];
        ((uint4*)(As + row * KPAD))[c] = v;
    }
    for (int i = tid; i < K * 12; i += 128) {
        int row = i / 12, c = i % 12;
        ((uint4*)(Bs + row * NPAD))[c] = ((const uint4*)(Wh + (size_t)row * 96))[c];
    }
    __syncthreads();

    int m0w = (wid & 1) * 32;
    int n0w = (wid >> 1) * 48;
    float acc[2][6][4];
    #pragma unroll
    for (int mi = 0; mi < 2; mi++)
        #pragma unroll
        for (int nj = 0; nj < 6; nj++)
            #pragma unroll
            for (int q = 0; q < 4; q++) acc[mi][nj][q] = 0.f;

    uint32_t aBase = smem_u32(As), bBase = smem_u32(Bs);
    #pragma unroll
    for (int ks = 0; ks < K / 16; ks++) {
        int k0 = ks * 16;
        uint32_t a[2][4];
        #pragma unroll
        for (int mi = 0; mi < 2; mi++) {
            uint32_t addr = aBase +
                (((m0w + mi * 16 + (lane & 7) + (lane & 8)) * KPAD + k0 + ((lane >> 4) << 3)) << 1);
            ldmatrix_x4(a[mi], addr);
        }
        uint32_t b[6][2];
        #pragma unroll
        for (int bj = 0; bj < 3; bj++) {
            uint32_t r[4];
            uint32_t addr = bBase +
                (((k0 + (lane & 15)) * NPAD + n0w + bj * 16 + ((lane >> 4) << 3)) << 1);
            ldmatrix_x4_t(r, addr);
            b[2 * bj][0] = r[0]; b[2 * bj][1] = r[1];
            b[2 * bj + 1][0] = r[2]; b[2 * bj + 1][1] = r[3];
        }
        #pragma unroll
        for (int mi = 0; mi < 2; mi++)
            #pragma unroll
            for (int nj = 0; nj < 6; nj++)
                mma16816(acc[mi][nj], a[mi], b[nj]);
    }

    #pragma unroll
    for (int mi = 0; mi < 2; mi++) {
        #pragma unroll
        for (int nj = 0; nj < 6; nj++) {
            int col = n0w + nj * 8 + 2 * (lane & 3);
            float bx = 0.f, by = 0.f;
            if (BIAS) { float2 bb = *(const float2*)(bias + col); bx = bb.x; by = bb.y; }
            int r = blockRow + m0w + mi * 16 + (lane >> 2);
            float v0 = fmaxf(acc[mi][nj][0] + bx, 0.f);
            float v1 = fmaxf(acc[mi][nj][1] + by, 0.f);
            float v2 = fmaxf(acc[mi][nj][2] + bx, 0.f);
            float v3 = fmaxf(acc[mi][nj][3] + by, 0.f);
            if (r < M) {
                __half2 h = __float22half2_rn(make_float2(v0, v1));
                hh[(size_t)r * HWORDS + (col >> 1)] = *(uint32_t*)&h;
            }
            if (r + 8 < M) {
                __half2 h = __float22half2_rn(make_float2(v2, v3));
                hh[(size_t)(r + 8) * HWORDS + (col >> 1)] = *(uint32_t*)&h;
            }
        }
    }
}

// ---------------- register-tiled fp32 GEMM, packed f32x2 FMA (layer3 + decoder) ----------------
template <int TN, bool RELU, bool WF32, bool WHALF>
__global__ void __launch_bounds__(128)
gemm_kernel(const float* __restrict__ A, const float* __restrict__ B,
            const float* __restrict__ bias, float* __restrict__ C,
            uint32_t* __restrict__ Chalf, float* __restrict__ C2,
            int M, int K, int lda, int ldc) {
    constexpr int BN = TN * 16;
    constexpr int BM = 64;
    constexpr int BK = 16;
    constexpr int TM = 8;
    __shared__ float As[BK][BM + 4];
    __shared__ float Bs[BK][BN];

    int tid = threadIdx.x;
    int tx = tid & 15;
    int ty = tid >> 4;
    int blockRow = blockIdx.x * BM;

    double acc[TM / 2][TN];
    #pragma unroll
    for (int i = 0; i < TM / 2; i++)
        #pragma unroll
        for (int j = 0; j < TN; j++) acc[i][j] = 0.0;

    for (int k0 = 0; k0 < K; k0 += BK) {
        #pragma unroll
        for (int r = 0; r < 2; r++) {
            int f = tid + r * 128;
            int row = f >> 2;
            int seg = f & 3;
            int gRow = blockRow + row;
            float4 v = make_float4(0.f, 0.f, 0.f, 0.f);
            if (gRow < M) v = *(const float4*)(A + (size_t)gRow * lda + k0 + seg * 4);
            As[seg * 4 + 0][row] = v.x;
            As[seg * 4 + 1][row] = v.y;
            As[seg * 4 + 2][row] = v.z;
            As[seg * 4 + 3][row] = v.w;
        }
        #pragma unroll
        for (int e = tid; e < BK * BN / 4; e += 128)
            ((float4*)Bs)[e] = ((const float4*)(B + (size_t)k0 * BN))[e];
        __syncthreads();
        #pragma unroll
        for (int kk = 0; kk < BK; kk++) {
            double a2[TM / 2];
            #pragma unroll
            for (int i = 0; i < TM / 2; i++)
                a2[i] = *(const double*)&As[kk][ty * TM + 2 * i];
            double b2[TN];
            #pragma unroll
            for (int j = 0; j < TN / 2; j++) {
                float2 t2 = *(const float2*)&Bs[kk][tx * TN + 2 * j];
                b2[2 * j + 0] = pack2(t2.x, t2.x);
                b2[2 * j + 1] = pack2(t2.y, t2.y);
            }
            #pragma unroll
            for (int i = 0; i < TM / 2; i++)
                #pragma unroll
                for (int j = 0; j < TN; j++) fma2(acc[i][j], a2[i], b2[j]);
        }
        __syncthreads();
    }

    #pragma unroll
    for (int i = 0; i < TM / 2; i++) {
        float2 col[TN];
        #pragma unroll
        for (int j = 0; j < TN; j++) col[j] = unpack2(acc[i][j]);
        #pragma unroll
        for (int half = 0; half < 2; half++) {
            int gRow = blockRow + ty * TM + 2 * i + half;
            if (gRow >= M) continue;
            float v[TN];
            #pragma unroll
            for (int j = 0; j < TN; j++) {
                float t = (half ? col[j].y : col[j].x) + bias[tx * TN + j];
                v[j] = RELU ? fmaxf(t, 0.f) : t;
            }
            if (WF32) {
                float* crow = C + (size_t)gRow * ldc + tx * TN;
                #pragma unroll
                for (int j = 0; j < TN / 2; j++)
                    *(float2*)(crow + 2 * j) = make_float2(v[2 * j], v[2 * j + 1]);
                if (C2) {
                    float* c2row = C2 + (size_t)gRow * ldc + tx * TN;
                    #pragma unroll
                    for (int j = 0; j < TN / 2; j++)
                        *(float2*)(c2row + 2 * j) = make_float2(v[2 * j], v[2 * j + 1]);
                }
            }
            if (WHALF && TN == 6) {
                uint32_t* hrow = Chalf + (size_t)gRow * HWORDS + tx * 3;
                #pragma unroll
                for (int j = 0; j < 3; j++) {
                    __half2 hv = __float22half2_rn(make_float2(v[2 * j], v[2 * j + 1]));
                    hrow[j] = *(uint32_t*)&hv;
                }
            }
        }
    }
}

// ---------------- aggregation: 2 edges per warp (half-warp each), uint4 h loads ----------------
// Each half-warp owns one edge; lanes sub=0..11 load 16B (8 channels) of the h row.
// Final half-warp combine via shfl_xor(16). OUT32: fp32 agg (layer 3); else fp16 agg.
template <bool OUT32>
__global__ void aggregate_kernel(const uint32_t* __restrict__ hh, int layer,
                                 float* __restrict__ aggf, uint32_t* __restrict__ aggh) {
    int warp = (blockIdx.x * blockDim.x + threadIdx.x) >> 5;
    int lane = threadIdx.x & 31;
    if (warp >= N_NODES) return;
    int beg = g_offsets[warp];
    int end = g_offsets[warp + 1];
    int h = lane >> 4;       // which edge of the pair
    int sub = lane & 15;     // channel-chunk lane; active if sub < 12
    bool act = sub < 12;

    double a[4] = {0.0, 0.0, 0.0, 0.0};   // head0: channels 8*sub .. 8*sub+7 (packed pairs)
    double b[4] = {0.0, 0.0, 0.0, 0.0};   // head1

    for (int jj = beg; jj < end; jj += 2) {
        int j = jj + h;
        bool valid = j < end;
        int jc = valid ? j : jj;
        int s = g_src_sorted[jc];
        float2 w = make_float2(0.f, 0.f);
        if (valid) w = g_ews[(size_t)jc * NUM_LAYERS + layer];
        uint4 u = make_uint4(0, 0, 0, 0);
        if (act) u = *(const uint4*)(hh + (size_t)s * HWORDS + sub * 4);
        double wa = pack2(w.x, w.x), wb = pack2(w.y, w.y);
        float2 x;
        x = __half22float2(*(__half2*)&u.x);
        { double dx = pack2(x.x, x.y); fma2(a[0], dx, wa); fma2(b[0], dx, wb); }
        x = __half22float2(*(__half2*)&u.y);
        { double dx = pack2(x.x, x.y); fma2(a[1], dx, wa); fma2(b[1], dx, wb); }
        x = __half22float2(*(__half2*)&u.z);
        { double dx = pack2(x.x, x.y); fma2(a[2], dx, wa); fma2(b[2], dx, wb); }
        x = __half22float2(*(__half2*)&u.w);
        { double dx = pack2(x.x, x.y); fma2(a[3], dx, wa); fma2(b[3], dx, wb); }
    }

    // combine the two half-warps
    float fa[8], fb[8];
    #pragma unroll
    for (int q = 0; q < 4; q++) {
        float2 t = unpack2(a[q]); fa[2 * q] = t.x; fa[2 * q + 1] = t.y;
        t = unpack2(b[q]);        fb[2 * q] = t.x; fb[2 * q + 1] = t.y;
    }
    #pragma unroll
    for (int q = 0; q < 8; q++) {
        fa[q] += __shfl_xor_sync(0xffffffffu, fa[q], 16);
        fb[q] += __shfl_xor_sync(0xffffffffu, fb[q], 16);
    }

    if (lane < 12) {
        if (OUT32) {
            float* o = aggf + (size_t)warp * (2 * H_DIM) + 8 * sub;
            *(float4*)(o)     = make_float4(fa[0], fa[1], fa[2], fa[3]);
            *(float4*)(o + 4) = make_float4(fa[4], fa[5], fa[6], fa[7]);
            float* o1 = o + 96;
            *(float4*)(o1)     = make_float4(fb[0], fb[1], fb[2], fb[3]);
            *(float4*)(o1 + 4) = make_float4(fb[4], fb[5], fb[6], fb[7]);
        } else {
            uint32_t* o = aggh + (size_t)warp * AGGW + 4 * sub;
            #pragma unroll
            for (int q = 0; q < 4; q++) {
                __half2 hv = __float22half2_rn(make_float2(fa[2 * q], fa[2 * q + 1]));
                o[q] = *(uint32_t*)&hv;
            }
            uint32_t* o1 = o + 48;
            #pragma unroll
            for (int q = 0; q < 4; q++) {
                __half2 hv = __float22half2_rn(make_float2(fb[2 * q], fb[2 * q + 1]));
                o1[q] = *(uint32_t*)&hv;
            }
        }
    }
}

// ---------------- launch (single stream) ----------------
extern "C" void kernel_launch(void* const* d_in, const int* in_sizes, int n_in,
                              void* d_out, int out_size) {
    const float* x       = (const float*)d_in[0];
    const int*   eidx    = (const int*)d_in[1];
    const float* enc_w   = (const float*)d_in[2];
    const float* enc_b   = (const float*)d_in[3];
    const float* dec_w   = (const float*)d_in[4];
    const float* dec_b   = (const float*)d_in[5];
    const float* conv_W  = (const float*)d_in[6];
    const float* conv_ew = (const float*)d_in[7];
    float* out = (float*)d_out;

    const int* src = eidx;
    const int* dst = eidx + E_EDGES;

    void *p_hfin, *p_hh, *p_agg, *p_aggh, *p_zb, *p_counts, *p_wh, *p_xh;
    cudaGetSymbolAddress(&p_hfin, g_hfin);
    cudaGetSymbolAddress(&p_hh, g_hhalf);
    cudaGetSymbolAddress(&p_agg, g_agg);
    cudaGetSymbolAddress(&p_aggh, g_aggh);
    cudaGetSymbolAddress(&p_zb, g_zero_bias);
    cudaGetSymbolAddress(&p_counts, g_counts);
    cudaGetSymbolAddress(&p_wh, g_whalf);
    cudaGetSymbolAddress(&p_xh, g_xh);
    float* hfin = (float*)p_hfin;
    uint32_t* hh = (uint32_t*)p_hh;
    float* agg = (float*)p_agg;
    uint32_t* aggh = (uint32_t*)p_aggh;
    const float* zb = (const float*)p_zb;
    const __half* wh = (const __half*)p_wh;
    const __half* xh = (const __half*)p_xh;

    constexpr int SMEM_CONV = (64 * 200 + 192 * 104) * 2;   // 65536
    constexpr int SMEM_ENC  = (64 * 136 + 128 * 104) * 2;   // 44032
    cudaFuncSetAttribute(mma_gemm<192, false>, cudaFuncAttributeMaxDynamicSharedMemorySize, SMEM_CONV);
    cudaFuncSetAttribute(mma_gemm<128, true>,  cudaFuncAttributeMaxDynamicSharedMemorySize, SMEM_ENC);

    // CSR build + fp16 prep
    cudaMemsetAsync(p_counts, 0, N_NODES * sizeof(int));
    hist_kernel<<<(E_EDGES + 255) / 256, 256>>>(dst);
    block_scan_kernel<<<NB_SCAN, 1024>>>();
    add_base_kernel<<<(N_NODES + 256) / 256, 256>>>();
    scatter_kernel<<<(E_EDGES + 255) / 256, 256>>>(src, dst, conv_ew);
    wprep_kernel<<<((12288 + 3 * 18432) / 2 + 255) / 256, 256>>>(enc_w, conv_W);
    xprep_kernel<<<(N_NODES * IN_DIM / 2 + 255) / 256, 256>>>(x);

    int gemmGrid = (N_NODES + 63) / 64;

    // encoder (HMMA): h = relu(x @ enc_w + enc_b) -> fp16
    mma_gemm<128, true><<<gemmGrid, 128, SMEM_ENC>>>(xh, wh, enc_b, hh, N_NODES);

    // layers 0..2 (HMMA)
    for (int l = 0; l < NUM_LAYERS - 1; l++) {
        aggregate_kernel<false><<<(N_NODES * 32 + 255) / 256, 256>>>(hh, l, nullptr, aggh);
        mma_gemm<192, false><<<gemmGrid, 128, SMEM_CONV>>>(
            (const __half*)aggh, wh + 12288 + l * 18432, nullptr, hh, N_NODES);
    }
    // layer 3 (fp32): h for decoder + duplicate into out tail
    aggregate_kernel<true><<<(N_NODES * 32 + 255) / 256, 256>>>(hh, NUM_LAYERS - 1, agg, nullptr);
    gemm_kernel<6, true, true, false><<<gemmGrid, 128>>>(
        agg, conv_W + (size_t)(NUM_LAYERS - 1) * 2 * H_DIM * H_DIM, zb, hfin, nullptr,
        out + (size_t)N_NODES * OUT_DIM, N_NODES, 2 * H_DIM, 2 * H_DIM, H_DIM);

    // decoder (fp32)
    gemm_kernel<4, false, true, false><<<gemmGrid, 128>>>(
        hfin, dec_w, dec_b, out, nullptr, nullptr, N_NODES, H_DIM, H_DIM, OUT_DIM);
    (void)in_sizes; (void)n_in; (void)out_size;
}

// round 14
// speedup vs baseline: 1.2572x; 1.0072x over previous
#include <cuda_runtime.h>
#include <cuda_fp16.h>
#include <cstdint>

#define N_NODES 50000
#define E_EDGES 800000
#define IN_DIM  128
#define H_DIM   96
#define OUT_DIM 64
#define NUM_LAYERS 4
#define NB_SCAN ((N_NODES + 1023) / 1024)
#define HWORDS  48   // 96 channels as half2 words

// ---------------- static device scratch ----------------
__device__ float    g_hfin[N_NODES * H_DIM];                 // final-layer fp32 h
__device__ uint32_t g_hh0[(size_t)N_NODES * HWORDS];         // h fp16, buffer 0
__device__ uint32_t g_hh1[(size_t)N_NODES * HWORDS];         // h fp16, buffer 1
__device__ float    g_agg[(size_t)N_NODES * 2 * H_DIM];      // fp32 agg (layer 3 only)
__device__ uint32_t g_xh[(size_t)N_NODES * IN_DIM / 2];      // x as half2
__device__ uint32_t g_whalf[(12288 + 3 * 18432) / 2];        // enc_w + conv_W[0..2] fp16
__device__ int      g_counts[N_NODES];
__device__ int      g_offsets[N_NODES + 1];
__device__ int      g_cursor[N_NODES];
__device__ int      g_src_sorted[E_EDGES];
__device__ float2   g_ews[(size_t)E_EDGES * NUM_LAYERS];
__device__ int      g_bsum[NB_SCAN + 1];
__device__ float    g_zero_bias[H_DIM];

// ---------------- helpers ----------------
__device__ __forceinline__ double pack2(float lo, float hi) {
    double d;
    asm("mov.b64 %0, {%1, %2};" : "=d"(d) : "f"(lo), "f"(hi));
    return d;
}
__device__ __forceinline__ void fma2(double& acc, double a, double b) {
    asm("fma.rn.f32x2 %0, %1, %2, %0;" : "+d"(acc) : "d"(a), "d"(b));
}
__device__ __forceinline__ float2 unpack2(double d) {
    float lo, hi;
    asm("mov.b64 {%0, %1}, %2;" : "=f"(lo), "=f"(hi) : "d"(d));
    return make_float2(lo, hi);
}
__device__ __forceinline__ uint32_t smem_u32(const void* p) {
    uint32_t a;
    asm("{ .reg .u64 t; cvta.to.shared.u64 t, %1; cvt.u32.u64 %0, t; }" : "=r"(a) : "l"(p));
    return a;
}
__device__ __forceinline__ void ldmatrix_x4(uint32_t* r, uint32_t addr) {
    asm volatile("ldmatrix.sync.aligned.m8n8.x4.shared.b16 {%0,%1,%2,%3}, [%4];"
                 : "=r"(r[0]), "=r"(r[1]), "=r"(r[2]), "=r"(r[3]) : "r"(addr));
}
__device__ __forceinline__ void ldmatrix_x4_t(uint32_t* r, uint32_t addr) {
    asm volatile("ldmatrix.sync.aligned.m8n8.x4.trans.shared.b16 {%0,%1,%2,%3}, [%4];"
                 : "=r"(r[0]), "=r"(r[1]), "=r"(r[2]), "=r"(r[3]) : "r"(addr));
}
__device__ __forceinline__ void mma16816(float* c, const uint32_t* a, const uint32_t* b) {
    asm volatile("mma.sync.aligned.m16n8k16.row.col.f32.f16.f16.f32 "
                 "{%0,%1,%2,%3},{%4,%5,%6,%7},{%8,%9},{%0,%1,%2,%3};"
                 : "+f"(c[0]), "+f"(c[1]), "+f"(c[2]), "+f"(c[3])
                 : "r"(a[0]), "r"(a[1]), "r"(a[2]), "r"(a[3]), "r"(b[0]), "r"(b[1]));
}

// ---------------- CSR build ----------------
__global__ void hist_kernel(const int* __restrict__ dst) {
    int e = blockIdx.x * blockDim.x + threadIdx.x;
    if (e < E_EDGES) atomicAdd(&g_counts[dst[e]], 1);
}

__global__ void block_scan_kernel() {
    __shared__ int sh[1024];
    int t = threadIdx.x;
    int i = blockIdx.x * 1024 + t;
    int v = (i < N_NODES) ? g_counts[i] : 0;
    sh[t] = v;
    __syncthreads();
    #pragma unroll
    for (int off = 1; off < 1024; off <<= 1) {
        int x = (t >= off) ? sh[t - off] : 0;
        __syncthreads();
        sh[t] += x;
        __syncthreads();
    }
    if (i < N_NODES) g_offsets[i] = sh[t] - v;
    if (t == 1023) g_bsum[blockIdx.x] = sh[1023];
}

__global__ void add_base_kernel() {
    __shared__ int pref[NB_SCAN + 1];
    if (threadIdx.x == 0) {
        int run = 0;
        #pragma unroll
        for (int i = 0; i < NB_SCAN; i++) { pref[i] = run; run += g_bsum[i]; }
        pref[NB_SCAN] = run;
    }
    __syncthreads();
    int i = blockIdx.x * blockDim.x + threadIdx.x;
    if (i < N_NODES) {
        int o = g_offsets[i] + pref[i >> 10];
        g_offsets[i] = o;
        g_cursor[i] = o;
    }
    if (i == N_NODES) g_offsets[N_NODES] = pref[NB_SCAN];
}

__global__ void scatter_kernel(const int* __restrict__ src,
                               const int* __restrict__ dst,
                               const float* __restrict__ conv_ew) {
    int e = blockIdx.x * blockDim.x + threadIdx.x;
    if (e >= E_EDGES) return;
    int d = dst[e];
    int pos = atomicAdd(&g_cursor[d], 1);
    g_src_sorted[pos] = src[e];
    #pragma unroll
    for (int l = 0; l < NUM_LAYERS; l++) {
        float w0 = conv_ew[(size_t)(l * 2 + 0) * E_EDGES + e];
        float w1 = conv_ew[(size_t)(l * 2 + 1) * E_EDGES + e];
        g_ews[(size_t)pos * NUM_LAYERS + l] = make_float2(w0, w1);
    }
}

// ---------------- fp16 prep ----------------
__global__ void wprep_kernel(const float* __restrict__ enc_w,
                             const float* __restrict__ conv_W) {
    int i = blockIdx.x * blockDim.x + threadIdx.x;
    const int total = (12288 + 3 * 18432) / 2;
    if (i >= total) return;
    int off = i * 2;
    float2 v = (off < 12288) ? *(const float2*)(enc_w + off)
                             : *(const float2*)(conv_W + (off - 12288));
    __half2 h = __float22half2_rn(v);
    g_whalf[i] = *(uint32_t*)&h;
}

__global__ void xprep_kernel(const float* __restrict__ x) {
    int i = blockIdx.x * blockDim.x + threadIdx.x;
    const int total = N_NODES * IN_DIM / 2;
    if (i >= total) return;
    float2 v = *(const float2*)(x + i * 2);
    __half2 h = __float22half2_rn(v);
    g_xh[i] = *(uint32_t*)&h;
}

// ---------------- per-node aggregation body (R11 code, writes word-row) ----------------
__device__ __forceinline__ void agg_node(const uint32_t* __restrict__ hh, int layer,
                                         int beg, int end, int lane, bool lo,
                                         uint32_t* __restrict__ orow /* 96-word row */) {
    float2 A0 = {0.f, 0.f}, B0 = {0.f, 0.f};
    float2 A1 = {0.f, 0.f}, B1 = {0.f, 0.f};
    int j = beg;
    for (; j + 7 < end; j += 8) {
        int s[8];
        float2 w[8];
        #pragma unroll
        for (int q = 0; q < 8; q++) {
            s[q] = g_src_sorted[j + q];
            w[q] = g_ews[(size_t)(j + q) * NUM_LAYERS + layer];
        }
        uint32_t ua[8], ub[8];
        #pragma unroll
        for (int q = 0; q < 8; q++) {
            const uint32_t* r = hh + (size_t)s[q] * HWORDS;
            ua[q] = r[lane];
            ub[q] = lo ? r[32 + lane] : 0;
        }
        #pragma unroll
        for (int q = 0; q < 8; q++) {
            float2 x = __half22float2(*(__half2*)&ua[q]);
            A0.x += w[q].x * x.x; A0.y += w[q].x * x.y;
            B0.x += w[q].y * x.x; B0.y += w[q].y * x.y;
            x = __half22float2(*(__half2*)&ub[q]);
            A1.x += w[q].x * x.x; A1.y += w[q].x * x.y;
            B1.x += w[q].y * x.x; B1.y += w[q].y * x.y;
        }
    }
    for (; j + 3 < end; j += 4) {
        int s[4];
        float2 w[4];
        #pragma unroll
        for (int q = 0; q < 4; q++) {
            s[q] = g_src_sorted[j + q];
            w[q] = g_ews[(size_t)(j + q) * NUM_LAYERS + layer];
        }
        uint32_t ua[4], ub[4];
        #pragma unroll
        for (int q = 0; q < 4; q++) {
            const uint32_t* r = hh + (size_t)s[q] * HWORDS;
            ua[q] = r[lane];
            ub[q] = lo ? r[32 + lane] : 0;
        }
        #pragma unroll
        for (int q = 0; q < 4; q++) {
            float2 x = __half22float2(*(__half2*)&ua[q]);
            A0.x += w[q].x * x.x; A0.y += w[q].x * x.y;
            B0.x += w[q].y * x.x; B0.y += w[q].y * x.y;
            x = __half22float2(*(__half2*)&ub[q]);
            A1.x += w[q].x * x.x; A1.y += w[q].x * x.y;
            B1.x += w[q].y * x.x; B1.y += w[q].y * x.y;
        }
    }
    for (; j < end; j++) {
        int s = g_src_sorted[j];
        float2 w = g_ews[(size_t)j * NUM_LAYERS + layer];
        const uint32_t* r = hh + (size_t)s * HWORDS;
        uint32_t u0 = r[lane];
        uint32_t u1 = lo ? r[32 + lane] : 0;
        float2 x = __half22float2(*(__half2*)&u0);
        A0.x += w.x * x.x; A0.y += w.x * x.y; B0.x += w.y * x.x; B0.y += w.y * x.y;
        x = __half22float2(*(__half2*)&u1);
        A1.x += w.x * x.x; A1.y += w.x * x.y; B1.x += w.y * x.x; B1.y += w.y * x.y;
    }
    __half2 hv;
    hv = __float22half2_rn(A0); orow[lane]      = *(uint32_t*)&hv;   // head0 ch 0..63
    hv = __float22half2_rn(B0); orow[48 + lane] = *(uint32_t*)&hv;   // head1 ch 0..63
    if (lo) {
        hv = __float22half2_rn(A1); orow[32 + lane] = *(uint32_t*)&hv;
        hv = __float22half2_rn(B1); orow[80 + lane] = *(uint32_t*)&hv;
    }
}

// ---------------- fused conv layer: aggregate (into SMEM) + HMMA GEMM ----------------
// CTA = 64 nodes, 256 threads (8 warps). A-tile built in SMEM by aggregation.
// hh_in != hh_out (double-buffered).
__global__ void __launch_bounds__(256)
fused_layer(const uint32_t* __restrict__ hh_in, int layer,
            const __half* __restrict__ Wh, uint32_t* __restrict__ hh_out, int M) {
    constexpr int K = 192, KPAD = 200, NPAD = 104;
    extern __shared__ __half sm[];
    __half* As = sm;                 // [64][200]
    __half* Bs = sm + 64 * KPAD;     // [192][104]
    int tid = threadIdx.x, lane = tid & 31, wid = tid >> 5;
    int blockRow = blockIdx.x * 64;
    bool lo = lane < 16;

    // load W tile
    for (int i = tid; i < K * 12; i += 256) {
        int row = i / 12, c = i % 12;
        ((uint4*)(Bs + row * NPAD))[c] = ((const uint4*)(Wh + (size_t)row * 96))[c];
    }

    // aggregation: warp wid handles nodes blockRow + wid*8 .. +7
    #pragma unroll 1
    for (int t = 0; t < 8; t++) {
        int row = wid * 8 + t;
        int node = blockRow + row;
        if (node < M) {
            int beg = g_offsets[node];
            int end = g_offsets[node + 1];
            agg_node(hh_in, layer, beg, end, lane, lo, (uint32_t*)(As + row * KPAD));
        }
    }
    __syncthreads();

    // HMMA GEMM: 8 warps, warp tile 16(M) x 48(N)
    int m0w = (wid & 3) * 16;
    int n0w = (wid >> 2) * 48;
    float acc[6][4];
    #pragma unroll
    for (int nj = 0; nj < 6; nj++)
        #pragma unroll
        for (int q = 0; q < 4; q++) acc[nj][q] = 0.f;

    uint32_t aBase = smem_u32(As), bBase = smem_u32(Bs);
    #pragma unroll
    for (int ks = 0; ks < K / 16; ks++) {
        int k0 = ks * 16;
        uint32_t a[4];
        {
            uint32_t addr = aBase +
                (((m0w + (lane & 7) + (lane & 8)) * KPAD + k0 + ((lane >> 4) << 3)) << 1);
            ldmatrix_x4(a, addr);
        }
        uint32_t b[6][2];
        #pragma unroll
        for (int bj = 0; bj < 3; bj++) {
            uint32_t r[4];
            uint32_t addr = bBase +
                (((k0 + (lane & 15)) * NPAD + n0w + bj * 16 + ((lane >> 4) << 3)) << 1);
            ldmatrix_x4_t(r, addr);
            b[2 * bj][0] = r[0]; b[2 * bj][1] = r[1];
            b[2 * bj + 1][0] = r[2]; b[2 * bj + 1][1] = r[3];
        }
        #pragma unroll
        for (int nj = 0; nj < 6; nj++)
            mma16816(acc[nj], a, b[nj]);
    }

    // epilogue: relu -> fp16 rows
    #pragma unroll
    for (int nj = 0; nj < 6; nj++) {
        int col = n0w + nj * 8 + 2 * (lane & 3);
        int r = blockRow + m0w + (lane >> 2);
        float v0 = fmaxf(acc[nj][0], 0.f);
        float v1 = fmaxf(acc[nj][1], 0.f);
        float v2 = fmaxf(acc[nj][2], 0.f);
        float v3 = fmaxf(acc[nj][3], 0.f);
        if (r < M) {
            __half2 h = __float22half2_rn(make_float2(v0, v1));
            hh_out[(size_t)r * HWORDS + (col >> 1)] = *(uint32_t*)&h;
        }
        if (r + 8 < M) {
            __half2 h = __float22half2_rn(make_float2(v2, v3));
            hh_out[(size_t)(r + 8) * HWORDS + (col >> 1)] = *(uint32_t*)&h;
        }
    }
}

// ---------------- HMMA GEMM (encoder) ----------------
template <int K, bool BIAS>
__global__ void __launch_bounds__(128)
mma_gemm(const __half* __restrict__ Ag, const __half* __restrict__ Wh,
         const float* __restrict__ bias, uint32_t* __restrict__ hh, int M) {
    constexpr int KPAD = (K == 192) ? 200 : 136;
    constexpr int NPAD = 104;
    extern __shared__ __half sm[];
    __half* As = sm;
    __half* Bs = sm + 64 * KPAD;
    int tid = threadIdx.x, lane = tid & 31, wid = tid >> 5;
    int blockRow = blockIdx.x * 64;

    constexpr int ACH = K / 8;
    for (int i = tid; i < 64 * ACH; i += 128) {
        int row = i / ACH, c = i % ACH;
        int gRow = blockRow + row;
        uint4 v = make_uint4(0, 0, 0, 0);
        if (gRow < M) v = ((const uint4*)(Ag + (size_t)gRow * K))[c];
        ((uint4*)(As + row * KPAD))[c] = v;
    }
    for (int i = tid; i < K * 12; i += 128) {
        int row = i / 12, c = i % 12;
        ((uint4*)(Bs + row * NPAD))[c] = ((const uint4*)(Wh + (size_t)row * 96))[c];
    }
    __syncthreads();

    int m0w = (wid & 1) * 32;
    int n0w = (wid >> 1) * 48;
    float acc[2][6][4];
    #pragma unroll
    for (int mi = 0; mi < 2; mi++)
        #pragma unroll
        for (int nj = 0; nj < 6; nj++)
            #pragma unroll
            for (int q = 0; q < 4; q++) acc[mi][nj][q] = 0.f;

    uint32_t aBase = smem_u32(As), bBase = smem_u32(Bs);
    #pragma unroll
    for (int ks = 0; ks < K / 16; ks++) {
        int k0 = ks * 16;
        uint32_t a[2][4];
        #pragma unroll
        for (int mi = 0; mi < 2; mi++) {
            uint32_t addr = aBase +
                (((m0w + mi * 16 + (lane & 7) + (lane & 8)) * KPAD + k0 + ((lane >> 4) << 3)) << 1);
            ldmatrix_x4(a[mi], addr);
        }
        uint32_t b[6][2];
        #pragma unroll
        for (int bj = 0; bj < 3; bj++) {
            uint32_t r[4];
            uint32_t addr = bBase +
                (((k0 + (lane & 15)) * NPAD + n0w + bj * 16 + ((lane >> 4) << 3)) << 1);
            ldmatrix_x4_t(r, addr);
            b[2 * bj][0] = r[0]; b[2 * bj][1] = r[1];
            b[2 * bj + 1][0] = r[2]; b[2 * bj + 1][1] = r[3];
        }
        #pragma unroll
        for (int mi = 0; mi < 2; mi++)
            #pragma unroll
            for (int nj = 0; nj < 6; nj++)
                mma16816(acc[mi][nj], a[mi], b[nj]);
    }

    #pragma unroll
    for (int mi = 0; mi < 2; mi++) {
        #pragma unroll
        for (int nj = 0; nj < 6; nj++) {
            int col = n0w + nj * 8 + 2 * (lane & 3);
            float bx = 0.f, by = 0.f;
            if (BIAS) { float2 bb = *(const float2*)(bias + col); bx = bb.x; by = bb.y; }
            int r = blockRow + m0w + mi * 16 + (lane >> 2);
            float v0 = fmaxf(acc[mi][nj][0] + bx, 0.f);
            float v1 = fmaxf(acc[mi][nj][1] + by, 0.f);
            float v2 = fmaxf(acc[mi][nj][2] + bx, 0.f);
            float v3 = fmaxf(acc[mi][nj][3] + by, 0.f);
            if (r < M) {
                __half2 h = __float22half2_rn(make_float2(v0, v1));
                hh[(size_t)r * HWORDS + (col >> 1)] = *(uint32_t*)&h;
            }
            if (r + 8 < M) {
                __half2 h = __float22half2_rn(make_float2(v2, v3));
                hh[(size_t)(r + 8) * HWORDS + (col >> 1)] = *(uint32_t*)&h;
            }
        }
    }
}

// ---------------- register-tiled fp32 GEMM, packed f32x2 FMA (layer3 + decoder) ----------------
template <int TN, bool RELU, bool WF32>
__global__ void __launch_bounds__(128)
gemm_kernel(const float* __restrict__ A, const float* __restrict__ B,
            const float* __restrict__ bias, float* __restrict__ C,
            float* __restrict__ C2, int M, int K, int lda, int ldc) {
    constexpr int BN = TN * 16;
    constexpr int BM = 64;
    constexpr int BK = 16;
    constexpr int TM = 8;
    __shared__ float As[BK][BM + 4];
    __shared__ float Bs[BK][BN];

    int tid = threadIdx.x;
    int tx = tid & 15;
    int ty = tid >> 4;
    int blockRow = blockIdx.x * BM;

    double acc[TM / 2][TN];
    #pragma unroll
    for (int i = 0; i < TM / 2; i++)
        #pragma unroll
        for (int j = 0; j < TN; j++) acc[i][j] = 0.0;

    for (int k0 = 0; k0 < K; k0 += BK) {
        #pragma unroll
        for (int r = 0; r < 2; r++) {
            int f = tid + r * 128;
            int row = f >> 2;
            int seg = f & 3;
            int gRow = blockRow + row;
            float4 v = make_float4(0.f, 0.f, 0.f, 0.f);
            if (gRow < M) v = *(const float4*)(A + (size_t)gRow * lda + k0 + seg * 4);
            As[seg * 4 + 0][row] = v.x;
            As[seg * 4 + 1][row] = v.y;
            As[seg * 4 + 2][row] = v.z;
            As[seg * 4 + 3][row] = v.w;
        }
        #pragma unroll
        for (int e = tid; e < BK * BN / 4; e += 128)
            ((float4*)Bs)[e] = ((const float4*)(B + (size_t)k0 * BN))[e];
        __syncthreads();
        #pragma unroll
        for (int kk = 0; kk < BK; kk++) {
            double a2[TM / 2];
            #pragma unroll
            for (int i = 0; i < TM / 2; i++)
                a2[i] = *(const double*)&As[kk][ty * TM + 2 * i];
            double b2[TN];
            #pragma unroll
            for (int j = 0; j < TN / 2; j++) {
                float2 t2 = *(const float2*)&Bs[kk][tx * TN + 2 * j];
                b2[2 * j + 0] = pack2(t2.x, t2.x);
                b2[2 * j + 1] = pack2(t2.y, t2.y);
            }
            #pragma unroll
            for (int i = 0; i < TM / 2; i++)
                #pragma unroll
                for (int j = 0; j < TN; j++) fma2(acc[i][j], a2[i], b2[j]);
        }
        __syncthreads();
    }

    #pragma unroll
    for (int i = 0; i < TM / 2; i++) {
        float2 col[TN];
        #pragma unroll
        for (int j = 0; j < TN; j++) col[j] = unpack2(acc[i][j]);
        #pragma unroll
        for (int half = 0; half < 2; half++) {
            int gRow = blockRow + ty * TM + 2 * i + half;
            if (gRow >= M) continue;
            float v[TN];
            #pragma unroll
            for (int j = 0; j < TN; j++) {
                float t = (half ? col[j].y : col[j].x) + bias[tx * TN + j];
                v[j] = RELU ? fmaxf(t, 0.f) : t;
            }
            if (WF32) {
                float* crow = C + (size_t)gRow * ldc + tx * TN;
                #pragma unroll
                for (int j = 0; j < TN / 2; j++)
                    *(float2*)(crow + 2 * j) = make_float2(v[2 * j], v[2 * j + 1]);
                if (C2) {
                    float* c2row = C2 + (size_t)gRow * ldc + tx * TN;
                    #pragma unroll
                    for (int j = 0; j < TN / 2; j++)
                        *(float2*)(c2row + 2 * j) = make_float2(v[2 * j], v[2 * j + 1]);
                }
            }
        }
    }
}

// ---------------- fp32 aggregation (layer 3) ----------------
__global__ void aggregate32_kernel(const uint32_t* __restrict__ hh, int layer,
                                   float* __restrict__ aggf) {
    int warp = (blockIdx.x * blockDim.x + threadIdx.x) >> 5;
    int lane = threadIdx.x & 31;
    if (warp >= N_NODES) return;
    int beg = g_offsets[warp];
    int end = g_offsets[warp + 1];
    bool lo = lane < 16;

    float2 A0 = {0.f, 0.f}, B0 = {0.f, 0.f};
    float2 A1 = {0.f, 0.f}, B1 = {0.f, 0.f};
    int j = beg;
    for (; j + 7 < end; j += 8) {
        int s[8];
        float2 w[8];
        #pragma unroll
        for (int q = 0; q < 8; q++) {
            s[q] = g_src_sorted[j + q];
            w[q] = g_ews[(size_t)(j + q) * NUM_LAYERS + layer];
        }
        uint32_t ua[8], ub[8];
        #pragma unroll
        for (int q = 0; q < 8; q++) {
            const uint32_t* r = hh + (size_t)s[q] * HWORDS;
            ua[q] = r[lane];
            ub[q] = lo ? r[32 + lane] : 0;
        }
        #pragma unroll
        for (int q = 0; q < 8; q++) {
            float2 x = __half22float2(*(__half2*)&ua[q]);
            A0.x += w[q].x * x.x; A0.y += w[q].x * x.y;
            B0.x += w[q].y * x.x; B0.y += w[q].y * x.y;
            x = __half22float2(*(__half2*)&ub[q]);
            A1.x += w[q].x * x.x; A1.y += w[q].x * x.y;
            B1.x += w[q].y * x.x; B1.y += w[q].y * x.y;
        }
    }
    for (; j < end; j++) {
        int s = g_src_sorted[j];
        float2 w = g_ews[(size_t)j * NUM_LAYERS + layer];
        const uint32_t* r = hh + (size_t)s * HWORDS;
        uint32_t u0 = r[lane];
        uint32_t u1 = lo ? r[32 + lane] : 0;
        float2 x = __half22float2(*(__half2*)&u0);
        A0.x += w.x * x.x; A0.y += w.x * x.y; B0.x += w.y * x.x; B0.y += w.y * x.y;
        x = __half22float2(*(__half2*)&u1);
        A1.x += w.x * x.x; A1.y += w.x * x.y; B1.x += w.y * x.x; B1.y += w.y * x.y;
    }
    float* o = aggf + (size_t)warp * (2 * H_DIM);
    *(float2*)(o + 2 * lane)       = A0;
    *(float2*)(o + 96 + 2 * lane)  = B0;
    if (lo) {
        *(float2*)(o + 64 + 2 * lane)  = A1;
        *(float2*)(o + 160 + 2 * lane) = B1;
    }
}

// ---------------- launch (single stream) ----------------
extern "C" void kernel_launch(void* const* d_in, const int* in_sizes, int n_in,
                              void* d_out, int out_size) {
    const float* x       = (const float*)d_in[0];
    const int*   eidx    = (const int*)d_in[1];
    const float* enc_w   = (const float*)d_in[2];
    const float* enc_b   = (const float*)d_in[3];
    const float* dec_w   = (const float*)d_in[4];
    const float* dec_b   = (const float*)d_in[5];
    const float* conv_W  = (const float*)d_in[6];
    const float* conv_ew = (const float*)d_in[7];
    float* out = (float*)d_out;

    const int* src = eidx;
    const int* dst = eidx + E_EDGES;

    void *p_hfin, *p_hh0, *p_hh1, *p_agg, *p_zb, *p_counts, *p_wh, *p_xh;
    cudaGetSymbolAddress(&p_hfin, g_hfin);
    cudaGetSymbolAddress(&p_hh0, g_hh0);
    cudaGetSymbolAddress(&p_hh1, g_hh1);
    cudaGetSymbolAddress(&p_agg, g_agg);
    cudaGetSymbolAddress(&p_zb, g_zero_bias);
    cudaGetSymbolAddress(&p_counts, g_counts);
    cudaGetSymbolAddress(&p_wh, g_whalf);
    cudaGetSymbolAddress(&p_xh, g_xh);
    float* hfin = (float*)p_hfin;
    uint32_t* hh0 = (uint32_t*)p_hh0;
    uint32_t* hh1 = (uint32_t*)p_hh1;
    float* agg = (float*)p_agg;
    const float* zb = (const float*)p_zb;
    const __half* wh = (const __half*)p_wh;
    const __half* xh = (const __half*)p_xh;

    constexpr int SMEM_FUSED = (64 * 200 + 192 * 104) * 2;   // 65536
    constexpr int SMEM_ENC   = (64 * 136 + 128 * 104) * 2;   // 44032
    cudaFuncSetAttribute(fused_layer, cudaFuncAttributeMaxDynamicSharedMemorySize, SMEM_FUSED);
    cudaFuncSetAttribute(mma_gemm<128, true>, cudaFuncAttributeMaxDynamicSharedMemorySize, SMEM_ENC);

    // CSR build + fp16 prep
    cudaMemsetAsync(p_counts, 0, N_NODES * sizeof(int));
    hist_kernel<<<(E_EDGES + 255) / 256, 256>>>(dst);
    block_scan_kernel<<<NB_SCAN, 1024>>>();
    add_base_kernel<<<(N_NODES + 256) / 256, 256>>>();
    scatter_kernel<<<(E_EDGES + 255) / 256, 256>>>(src, dst, conv_ew);
    wprep_kernel<<<((12288 + 3 * 18432) / 2 + 255) / 256, 256>>>(enc_w, conv_W);
    xprep_kernel<<<(N_NODES * IN_DIM / 2 + 255) / 256, 256>>>(x);

    int gemmGrid = (N_NODES + 63) / 64;

    // encoder (HMMA): hh0 = relu(x @ enc_w + enc_b)
    mma_gemm<128, true><<<gemmGrid, 128, SMEM_ENC>>>(xh, wh, enc_b, hh0, N_NODES);

    // layers 0..2: fused aggregate+GEMM, double-buffered
    uint32_t* cur = hh0;
    uint32_t* nxt = hh1;
    for (int l = 0; l < NUM_LAYERS - 1; l++) {
        fused_layer<<<gemmGrid, 256, SMEM_FUSED>>>(cur, l, wh + 12288 + l * 18432, nxt, N_NODES);
        uint32_t* t = cur; cur = nxt; nxt = t;
    }
    // layer 3 (fp32): aggregate + GEMM; h for decoder + duplicate into out tail
    aggregate32_kernel<<<(N_NODES * 32 + 255) / 256, 256>>>(cur, NUM_LAYERS - 1, agg);
    gemm_kernel<6, true, true><<<gemmGrid, 128>>>(
        agg, conv_W + (size_t)(NUM_LAYERS - 1) * 2 * H_DIM * H_DIM, zb, hfin,
        out + (size_t)N_NODES * OUT_DIM, N_NODES, 2 * H_DIM, 2 * H_DIM, H_DIM);

    // decoder (fp32)
    gemm_kernel<4, false, true><<<gemmGrid, 128>>>(
        hfin, dec_w, dec_b, out, nullptr, N_NODES, H_DIM, H_DIM, OUT_DIM);
    (void)in_sizes; (void)n_in; (void)out_size;
}